// round 14
// baseline (speedup 1.0000x reference)
#include <cuda_runtime.h>
#include <cuda_bf16.h>
#include <cstdint>

#define NN 100000
#define NE 800000
#define F  128
#define NT 782              // ceil(NN/128) node tiles
#define NB 391              // ceil(NN/256) scan blocks
#define LDA 136             // smem row stride in bf16 elements
#define REG_BYTES (128 * LDA * 2)   // 34816
#define PKF 192             // pack row stride in floats (512B hs + 256B slhp)

// fused kernel smem layout (bytes) — no As region; 2 CTAs/SM
#define AH_OFF  0                        // 34816: bf16 hp
#define BH_OFF  (AH_OFF + REG_BYTES)     // 34816: bf16 v (hi)
#define EW_OFF  (BH_OFF + REG_BYTES)     // 16384
#define LEW_OFF (EW_OFF + 16384)         // 16384
#define SGN_OFF (LEW_OFF + 16384)        // 4096
#define CNT_OFF (SGN_OFF + 4096)
#define SMEM_FUSED (CNT_OFF + 16)        // 106512

// ---------------- scratch ----------------------------------------------------
__device__ int      g_indeg_i [NN];
__device__ int      g_outdeg_i[NN];
__device__ int      g_rowstart[NN];
__device__ int      g_cursor  [NN];
__device__ float    g_rin     [NN];
__device__ int      g_blksum  [512];
__device__ unsigned g_csr     [NE];
__device__ float    g_pack [(size_t)NN * PKF];   // per node: 128 f32 hs | 128 bf16 slhp
__device__ float    g_lew  [32 * F];
__device__ unsigned g_lewsgn[32 * 32];
__device__ __nv_bfloat16 g_w1h[F * F], g_w1l[F * F];
__device__ __nv_bfloat16 g_w2h[F * F], g_w2l[F * F];
__device__ __nv_bfloat16 g_vh [F * F], g_vl [F * F];

// ---------------- helpers ----------------------------------------------------
__device__ __forceinline__ uint32_t smem_to_u32(const void* p) {
    uint32_t a;
    asm("{ .reg .u64 t; cvta.to.shared.u64 t, %1; cvt.u32.u64 %0, t; }" : "=r"(a) : "l"(p));
    return a;
}

__device__ __forceinline__ void ldsm4(uint32_t& r0, uint32_t& r1, uint32_t& r2, uint32_t& r3,
                                      uint32_t addr) {
    asm volatile("ldmatrix.sync.aligned.m8n8.x4.shared.b16 {%0,%1,%2,%3}, [%4];"
                 : "=r"(r0), "=r"(r1), "=r"(r2), "=r"(r3) : "r"(addr));
}

__device__ __forceinline__ void mma_bf16(float* c, const uint32_t* a, const uint32_t* b) {
    asm volatile("mma.sync.aligned.m16n8k16.row.col.f32.bf16.bf16.f32 "
                 "{%0,%1,%2,%3}, {%4,%5,%6,%7}, {%8,%9}, {%0,%1,%2,%3};"
                 : "+f"(c[0]), "+f"(c[1]), "+f"(c[2]), "+f"(c[3])
                 : "r"(a[0]), "r"(a[1]), "r"(a[2]), "r"(a[3]), "r"(b[0]), "r"(b[1]));
}

__device__ __forceinline__ void split4(float4 x, uint2& H, uint2& L) {
    float xs[4] = {x.x, x.y, x.z, x.w};
    unsigned short h[4], l[4];
#pragma unroll
    for (int j = 0; j < 4; j++) {
        __nv_bfloat16 bh = __float2bfloat16(xs[j]);
        float r = xs[j] - __bfloat162float(bh);
        __nv_bfloat16 bl = __float2bfloat16(r);
        h[j] = __bfloat16_as_ushort(bh);
        l[j] = __bfloat16_as_ushort(bl);
    }
    H = make_uint2((uint32_t)h[0] | ((uint32_t)h[1] << 16),
                   (uint32_t)h[2] | ((uint32_t)h[3] << 16));
    L = make_uint2((uint32_t)l[0] | ((uint32_t)l[1] << 16),
                   (uint32_t)l[2] | ((uint32_t)l[3] << 16));
}

// ---------------- CSR build --------------------------------------------------
__global__ void k_count(const int* __restrict__ src, const int* __restrict__ dst) {
    int e = blockIdx.x * blockDim.x + threadIdx.x;
    if (e < NE) {
        atomicAdd(&g_indeg_i [dst[e]], 1);
        atomicAdd(&g_outdeg_i[src[e]], 1);
    }
}

__global__ void k_scan1() {
    __shared__ int swarp[8];
    int t = threadIdx.x, b = blockIdx.x;
    int i = b * 256 + t;
    int v = (i < NN) ? g_indeg_i[i] : 0;
    int x = v;
    int lane = t & 31, w = t >> 5;
#pragma unroll
    for (int o = 1; o < 32; o <<= 1) {
        int y = __shfl_up_sync(0xffffffffu, x, o);
        if (lane >= o) x += y;
    }
    if (lane == 31) swarp[w] = x;
    __syncthreads();
    if (w == 0) {
        int s = (lane < 8) ? swarp[lane] : 0;
#pragma unroll
        for (int o = 1; o < 8; o <<= 1) {
            int y = __shfl_up_sync(0xffffffffu, s, o);
            if (lane >= o) s += y;
        }
        if (lane < 8) swarp[lane] = s;
    }
    __syncthreads();
    int off = (w > 0) ? swarp[w - 1] : 0;
    if (i < NN) g_rowstart[i] = x - v + off;
    if (t == 255) g_blksum[b] = x + off;
}

__global__ void k_scan2() {
    __shared__ int swarp[16];
    int t = threadIdx.x;
    int v = (t < NB) ? g_blksum[t] : 0;
    int x = v;
    int lane = t & 31, w = t >> 5;
#pragma unroll
    for (int o = 1; o < 32; o <<= 1) {
        int y = __shfl_up_sync(0xffffffffu, x, o);
        if (lane >= o) x += y;
    }
    if (lane == 31) swarp[w] = x;
    __syncthreads();
    if (w == 0) {
        int s = (lane < 16) ? swarp[lane] : 0;
#pragma unroll
        for (int o = 1; o < 16; o <<= 1) {
            int y = __shfl_up_sync(0xffffffffu, s, o);
            if (lane >= o) s += y;
        }
        if (lane < 16) swarp[lane] = s;
    }
    __syncthreads();
    int off = (w > 0) ? swarp[w - 1] : 0;
    if (t < NB) g_blksum[t] = x - v + off;
}

__global__ void k_scan3() {
    int i = blockIdx.x * 256 + threadIdx.x;
    if (i < NN) {
        int r = g_rowstart[i] + g_blksum[blockIdx.x];
        g_rowstart[i] = r;
        g_cursor[i]   = r;
        g_rin[i]      = rsqrtf(fmaxf((float)g_indeg_i[i], 1.0f));
    }
}

__global__ void k_scatter(const int* __restrict__ src, const int* __restrict__ dst,
                          const int* __restrict__ eattr) {
    int e = blockIdx.x * blockDim.x + threadIdx.x;
    if (e < NE) {
        int d = dst[e];
        int pos = atomicAdd(&g_cursor[d], 1);
        g_csr[pos] = (unsigned)src[e] | ((unsigned)eattr[e] << 17);
    }
}

// ---------------- weights -> bf16 hi/lo B^T images --------------------------
__global__ void k_wprep(const float* __restrict__ w1, const float* __restrict__ w2,
                        const float* __restrict__ v) {
    int idx = blockIdx.x * 256 + threadIdx.x;
    if (idx >= 12288) return;
    int mat = idx >> 12;
    int rem = idx & 4095;
    int o  = rem >> 5;
    int k0 = (rem & 31) * 4;
    const float* src = (mat == 0) ? w1 : (mat == 1) ? w2 : v;
    __nv_bfloat16* hi = (mat == 0) ? g_w1h : (mat == 1) ? g_w2h : g_vh;
    __nv_bfloat16* lo = (mat == 0) ? g_w1l : (mat == 1) ? g_w2l : g_vl;
    float4 x;
    x.x = src[(size_t)(k0 + 0) * F + o];
    x.y = src[(size_t)(k0 + 1) * F + o];
    x.z = src[(size_t)(k0 + 2) * F + o];
    x.w = src[(size_t)(k0 + 3) * F + o];
    uint2 H, L; split4(x, H, L);
    *reinterpret_cast<uint2*>(&hi[o * F + k0]) = H;
    *reinterpret_cast<uint2*>(&lo[o * F + k0]) = L;
}

// ---------------- bond -> log|ew| + sign nibbles ----------------------------
__global__ void k_eprep(const float* __restrict__ bond) {
    int t = blockIdx.x;
    int g = threadIdx.x;
    float4 e = *reinterpret_cast<const float4*>(&bond[t * F + g * 4]);
    float4 le;
    le.x = __logf(fabsf(e.x));
    le.y = __logf(fabsf(e.y));
    le.z = __logf(fabsf(e.z));
    le.w = __logf(fabsf(e.w));
    *reinterpret_cast<float4*>(&g_lew[t * F + g * 4]) = le;
    unsigned sgn =  (__float_as_uint(e.x) >> 31)
                 | ((__float_as_uint(e.y) >> 31) << 1)
                 | ((__float_as_uint(e.z) >> 31) << 2)
                 | ((__float_as_uint(e.w) >> 31) << 3);
    g_lewsgn[t * 32 + g] = sgn;
}

// ---------------- fused dual node GEMM via mma.sync (512 threads) -----------
__global__ __launch_bounds__(512, 1) void k_node_mma(const float* __restrict__ feat,
                                                     const float* __restrict__ w2full) {
    extern __shared__ __align__(16) unsigned char smem[];
    __nv_bfloat16* Ah = (__nv_bfloat16*)smem;
    __nv_bfloat16* Al = Ah + 128 * LDA;
    __nv_bfloat16* Bw[3];
    Bw[0] = Al    + 128 * LDA;
    Bw[1] = Bw[0] + 128 * LDA;
    Bw[2] = Bw[1] + 128 * LDA;

    const int tid = threadIdx.x, lane = tid & 31, wid = tid >> 5;
    const int bid = blockIdx.x;

    {
        int r = tid >> 2, hf = tid & 3;
        int n = bid * 128 + r;
        float s = 0.0f;
        if (n < NN) s = rsqrtf(fmaxf((float)g_outdeg_i[n], 1.0f));
#pragma unroll
        for (int q = 0; q < 8; q++) {
            int k0 = hf * 32 + q * 4;
            float4 x = make_float4(0.f, 0.f, 0.f, 0.f);
            if (n < NN) {
                x = *reinterpret_cast<const float4*>(&feat[(size_t)n * F + k0]);
                x.x *= s; x.y *= s; x.z *= s; x.w *= s;
            }
            uint2 H, L; split4(x, H, L);
            *reinterpret_cast<uint2*>(&Ah[r * LDA + k0]) = H;
            *reinterpret_cast<uint2*>(&Al[r * LDA + k0]) = L;
        }
    }
    {
        const uint4* s0 = (const uint4*)g_w1h;
        const uint4* s1 = (const uint4*)g_w1l;
        const uint4* s2 = (const uint4*)g_w2h;
#pragma unroll
        for (int i = 0; i < 4; i++) {
            int idx = tid + i * 512;
            int row = idx >> 4, col = idx & 15;
            ((uint4*)Bw[0])[row * 17 + col] = s0[idx];
            ((uint4*)Bw[1])[row * 17 + col] = s1[idx];
            ((uint4*)Bw[2])[row * 17 + col] = s2[idx];
        }
    }
    __syncthreads();

    const int warp_m = wid & 1, warp_n = wid >> 1;
    const uint32_t sbase = smem_to_u32(smem);
    const uint32_t aAh = sbase, aAl = sbase + REG_BYTES;
    const int nl0 = (warp_n & 3) * 32;

    float c[4][4][4];
#pragma unroll
    for (int i = 0; i < 4; i++)
#pragma unroll
        for (int j = 0; j < 4; j++)
#pragma unroll
            for (int q = 0; q < 4; q++) c[i][j][q] = 0.f;

    const int npass = (warp_n < 4) ? 3 : 1;
#pragma unroll 1
    for (int p = 0; p < npass; p++) {
        uint32_t Abase = (p == 2) ? aAl : aAh;
        int bsel = (warp_n < 4) ? ((p == 1) ? 1 : 0) : 2;
        uint32_t Bbase = sbase + (uint32_t)(2 + bsel) * REG_BYTES;
#pragma unroll
        for (int ks = 0; ks < 8; ks++) {
            int k0 = ks * 16;
            uint32_t a[4][4];
#pragma unroll
            for (int i = 0; i < 4; i++) {
                int row = warp_m * 64 + i * 16 + (lane & 15);
                ldsm4(a[i][0], a[i][1], a[i][2], a[i][3],
                      Abase + (uint32_t)(row * LDA + k0 + ((lane >> 4) << 3)) * 2);
            }
            uint32_t b[4][2];
#pragma unroll
            for (int jj = 0; jj < 2; jj++) {
                int o = nl0 + jj * 16 + (lane & 7) + ((lane >> 4) << 3);
                uint32_t r0, r1, r2, r3;
                ldsm4(r0, r1, r2, r3,
                      Bbase + (uint32_t)(o * LDA + k0 + (((lane >> 3) & 1) << 3)) * 2);
                b[jj * 2][0] = r0; b[jj * 2][1] = r1;
                b[jj * 2 + 1][0] = r2; b[jj * 2 + 1][1] = r3;
            }
#pragma unroll
            for (int i = 0; i < 4; i++)
#pragma unroll
                for (int j = 0; j < 4; j++)
                    mma_bf16(c[i][j], a[i], b[j]);
        }
    }

    const int colbase = warp_n * 32;
    unsigned* packu = (unsigned*)g_pack;
#pragma unroll
    for (int i = 0; i < 4; i++) {
        int r0 = warp_m * 64 + i * 16 + (lane >> 2);
        int n0 = bid * 128 + r0;
        int n1 = n0 + 8;
#pragma unroll
        for (int j = 0; j < 4; j++) {
            int col = colbase + j * 8 + (lane & 3) * 2;
            if (col < 128) {
                if (n0 < NN)
                    *reinterpret_cast<float2*>(&g_pack[(size_t)n0 * PKF + col]) =
                        make_float2(c[i][j][0], c[i][j][1]);
                if (n1 < NN)
                    *reinterpret_cast<float2*>(&g_pack[(size_t)n1 * PKF + col]) =
                        make_float2(c[i][j][2], c[i][j][3]);
            } else {
                int c2 = col - 128;
                float2 bias = *reinterpret_cast<const float2*>(&w2full[(size_t)128 * F + c2]);
                if (n0 < NN) {
                    float t0 = tanhf(c[i][j][0] + bias.x);
                    float t1 = tanhf(c[i][j][1] + bias.y);
                    float l0 = __logf(fabsf(t0)) - 1.0f;
                    float l1 = __logf(fabsf(t1)) - 1.0f;
                    float s0 = (t0 < 0.f) ? -l0 : l0;
                    float s1 = (t1 < 0.f) ? -l1 : l1;
                    unsigned pk = (unsigned)__bfloat16_as_ushort(__float2bfloat16(s0))
                                | ((unsigned)__bfloat16_as_ushort(__float2bfloat16(s1)) << 16);
                    packu[(size_t)n0 * PKF + 128 + (c2 >> 1)] = pk;
                }
                if (n1 < NN) {
                    float t0 = tanhf(c[i][j][2] + bias.x);
                    float t1 = tanhf(c[i][j][3] + bias.y);
                    float l0 = __logf(fabsf(t0)) - 1.0f;
                    float l1 = __logf(fabsf(t1)) - 1.0f;
                    float s0 = (t0 < 0.f) ? -l0 : l0;
                    float s1 = (t1 < 0.f) ? -l1 : l1;
                    unsigned pk = (unsigned)__bfloat16_as_ushort(__float2bfloat16(s0))
                                | ((unsigned)__bfloat16_as_ushort(__float2bfloat16(s1)) << 16);
                    packu[(size_t)n1 * PKF + 128 + (c2 >> 1)] = pk;
                }
            }
        }
    }
}

// ---------------- fused gather + final GEMM (1024 threads, 2 CTA/SM) --------
// Phase 1: dynamic-row gather -> as written DIRECTLY to out (fp32 global),
//          hp -> bf16 smem image.
// Phase 2: single-pass MMA hp_bf16 @ v_hi; epilogue out = (out + C) * rin.
__global__ __launch_bounds__(1024, 2) void k_fused(const float* __restrict__ bond,
                                                   float* __restrict__ out) {
    extern __shared__ __align__(16) unsigned char smem[];
    __nv_bfloat16* Ah = (__nv_bfloat16*)(smem + AH_OFF);
    float*        ewS  = (float*)(smem + EW_OFF);
    float*        lewS = (float*)(smem + LEW_OFF);
    unsigned*     sgnS = (unsigned*)(smem + SGN_OFF);
    int*          cnt  = (int*)(smem + CNT_OFF);

    const int tid = threadIdx.x, lane = tid & 31, wid = tid >> 5;
    const int bid = blockIdx.x;
    const int g = lane;

    // stage tables + v(hi) tile; init row counter
    {
        const uint4* s0 = (const uint4*)g_vh;
        uint4* d0 = (uint4*)(smem + BH_OFF);
#pragma unroll
        for (int i = 0; i < 2; i++) {
            int idx = tid + i * 1024;
            int row = idx >> 4, col = idx & 15;
            d0[row * 17 + col] = s0[idx];
        }
#pragma unroll
        for (int i = 0; i < 4; i++) {
            int idx = tid + i * 1024;
            ewS[idx]  = bond[idx];
            lewS[idx] = g_lew[idx];
        }
        if (tid < 1024) sgnS[tid] = g_lewsgn[tid];
        if (tid == 0) *cnt = 0;
    }
    __syncthreads();

    const float4* pk4 = (const float4*)g_pack;   // 48 float4 per row
    const uint2*  pk2 = (const uint2*)g_pack;    // 96 uint2 per row; slhp at +64
    const float4* ew4 = (const float4*)ewS;
    const float4* lw4 = (const float4*)lewS;

    // Phase 1: gather, dynamic row assignment
    for (;;) {
        int r;
        if (lane == 0) r = atomicAdd(cnt, 1);
        r = __shfl_sync(0xffffffffu, r, 0);
        if (r >= 128) break;
        int n = bid * 128 + r;

        float4 as = make_float4(0.f, 0.f, 0.f, 0.f);
        float4 al = make_float4(0.f, 0.f, 0.f, 0.f);
        unsigned sg = 0;
        int deg = 0;

        if (n < NN) {
            int base = g_rowstart[n];
            deg = g_indeg_i[n];
            int i = 0;
            for (; i + 2 <= deg; i += 2) {
                unsigned c0 = __ldg(&g_csr[base + i]);
                unsigned c1 = __ldg(&g_csr[base + i + 1]);
                int s0 = c0 & 0x1FFFF, a0 = c0 >> 17;
                int s1 = c1 & 0x1FFFF, a1 = c1 >> 17;
                float4 h0 = __ldg(pk4 + (size_t)s0 * 48 + g);
                float4 h1 = __ldg(pk4 + (size_t)s1 * 48 + g);
                uint2  x0 = __ldg(pk2 + (size_t)s0 * 96 + 64 + g);
                uint2  x1 = __ldg(pk2 + (size_t)s1 * 96 + 64 + g);
                float4 e0 = ew4[a0 * 32 + g];
                float4 e1 = ew4[a1 * 32 + g];
                float4 w0 = lw4[a0 * 32 + g];
                float4 w1 = lw4[a1 * 32 + g];
                unsigned es = sgnS[a0 * 32 + g] ^ sgnS[a1 * 32 + g];

                as.x += h0.x*e0.x + h1.x*e1.x;
                as.y += h0.y*e0.y + h1.y*e1.y;
                as.z += h0.z*e0.z + h1.z*e1.z;
                as.w += h0.w*e0.w + h1.w*e1.w;

                float f00 = __uint_as_float((x0.x & 0xffffu) << 16);
                float f01 = __uint_as_float(x0.x & 0xffff0000u);
                float f02 = __uint_as_float((x0.y & 0xffffu) << 16);
                float f03 = __uint_as_float(x0.y & 0xffff0000u);
                float f10 = __uint_as_float((x1.x & 0xffffu) << 16);
                float f11 = __uint_as_float(x1.x & 0xffff0000u);
                float f12 = __uint_as_float((x1.y & 0xffffu) << 16);
                float f13 = __uint_as_float(x1.y & 0xffff0000u);

                al.x += (w0.x - fabsf(f00)) + (w1.x - fabsf(f10));
                al.y += (w0.y - fabsf(f01)) + (w1.y - fabsf(f11));
                al.z += (w0.z - fabsf(f02)) + (w1.z - fabsf(f12));
                al.w += (w0.w - fabsf(f03)) + (w1.w - fabsf(f13));

                unsigned b0 =  ((~(x0.x >> 15)) & 1u)
                            | (((~(x0.x >> 31)) & 1u) << 1)
                            | (((~(x0.y >> 15)) & 1u) << 2)
                            | (((~(x0.y >> 31)) & 1u) << 3);
                unsigned b1 =  ((~(x1.x >> 15)) & 1u)
                            | (((~(x1.x >> 31)) & 1u) << 1)
                            | (((~(x1.y >> 15)) & 1u) << 2)
                            | (((~(x1.y >> 31)) & 1u) << 3);
                sg ^= es ^ b0 ^ b1;
            }
            if (i < deg) {
                unsigned c0 = __ldg(&g_csr[base + i]);
                int s0 = c0 & 0x1FFFF, a0 = c0 >> 17;
                float4 h0 = __ldg(pk4 + (size_t)s0 * 48 + g);
                uint2  x0 = __ldg(pk2 + (size_t)s0 * 96 + 64 + g);
                float4 e0 = ew4[a0 * 32 + g];
                float4 w0 = lw4[a0 * 32 + g];
                unsigned es = sgnS[a0 * 32 + g];

                as.x += h0.x*e0.x; as.y += h0.y*e0.y;
                as.z += h0.z*e0.z; as.w += h0.w*e0.w;

                float f00 = __uint_as_float((x0.x & 0xffffu) << 16);
                float f01 = __uint_as_float(x0.x & 0xffff0000u);
                float f02 = __uint_as_float((x0.y & 0xffffu) << 16);
                float f03 = __uint_as_float(x0.y & 0xffff0000u);
                al.x += w0.x - fabsf(f00);
                al.y += w0.y - fabsf(f01);
                al.z += w0.z - fabsf(f02);
                al.w += w0.w - fabsf(f03);
                unsigned b0 =  ((~(x0.x >> 15)) & 1u)
                            | (((~(x0.x >> 31)) & 1u) << 1)
                            | (((~(x0.y >> 15)) & 1u) << 2)
                            | (((~(x0.y >> 31)) & 1u) << 3);
                sg ^= es ^ b0;
            }

            // as -> out directly (re-read in epilogue; visible after __syncthreads)
            *reinterpret_cast<float4*>(&out[(size_t)n * F + g * 4]) = as;
        }

        // hp = sign * exp(al + deg) -> bf16 smem image
        float hx = 0.f, hy = 0.f, hz = 0.f, hw = 0.f;
        if (n < NN) {
            float dc = (float)deg;
            hx = __expf(al.x + dc); if (sg & 1u) hx = -hx;
            hy = __expf(al.y + dc); if (sg & 2u) hy = -hy;
            hz = __expf(al.z + dc); if (sg & 4u) hz = -hz;
            hw = __expf(al.w + dc); if (sg & 8u) hw = -hw;
        }
        unsigned p0 = (unsigned)__bfloat16_as_ushort(__float2bfloat16(hx))
                    | ((unsigned)__bfloat16_as_ushort(__float2bfloat16(hy)) << 16);
        unsigned p1 = (unsigned)__bfloat16_as_ushort(__float2bfloat16(hz))
                    | ((unsigned)__bfloat16_as_ushort(__float2bfloat16(hw)) << 16);
        *reinterpret_cast<uint2*>(&Ah[r * LDA + g * 4]) = make_uint2(p0, p1);
    }
    __syncthreads();

    // Phase 2: single-pass MMA 128x128, 32 warps (4 x 8 of 32x16 tiles)
    const int warp_m = wid & 3, warp_n = wid >> 2;
    const uint32_t sbase = smem_to_u32(smem);
    const int nl0 = warp_n * 16;

    float c[2][2][4];
#pragma unroll
    for (int i = 0; i < 2; i++)
#pragma unroll
        for (int j = 0; j < 2; j++)
#pragma unroll
            for (int q = 0; q < 4; q++) c[i][j][q] = 0.f;

    {
        uint32_t Abase = sbase + AH_OFF;
        uint32_t Bbase = sbase + BH_OFF;
#pragma unroll
        for (int ks = 0; ks < 8; ks++) {
            int k0 = ks * 16;
            uint32_t a[2][4];
#pragma unroll
            for (int i = 0; i < 2; i++) {
                int row = warp_m * 32 + i * 16 + (lane & 15);
                ldsm4(a[i][0], a[i][1], a[i][2], a[i][3],
                      Abase + (uint32_t)(row * LDA + k0 + ((lane >> 4) << 3)) * 2);
            }
            uint32_t b[2][2];
            {
                int o = nl0 + (lane & 7) + ((lane >> 4) << 3);
                uint32_t r0, r1, r2, r3;
                ldsm4(r0, r1, r2, r3,
                      Bbase + (uint32_t)(o * LDA + k0 + (((lane >> 3) & 1) << 3)) * 2);
                b[0][0] = r0; b[0][1] = r1;
                b[1][0] = r2; b[1][1] = r3;
            }
#pragma unroll
            for (int i = 0; i < 2; i++)
#pragma unroll
                for (int j = 0; j < 2; j++)
                    mma_bf16(c[i][j], a[i], b[j]);
        }
    }

    // epilogue: out = (out + C) * rin   (RMW; phase-1 wrote the sum part)
#pragma unroll
    for (int i = 0; i < 2; i++) {
        int r0 = warp_m * 32 + i * 16 + (lane >> 2);
        int n0 = bid * 128 + r0;
        int n1 = n0 + 8;
        float rin0 = (n0 < NN) ? g_rin[n0] : 0.f;
        float rin1 = (n1 < NN) ? g_rin[n1] : 0.f;
#pragma unroll
        for (int j = 0; j < 2; j++) {
            int col = nl0 + j * 8 + (lane & 3) * 2;
            if (n0 < NN) {
                float2* p = reinterpret_cast<float2*>(&out[(size_t)n0 * F + col]);
                float2 prev = *p;
                *p = make_float2((prev.x + c[i][j][0]) * rin0,
                                 (prev.y + c[i][j][1]) * rin0);
            }
            if (n1 < NN) {
                float2* p = reinterpret_cast<float2*>(&out[(size_t)n1 * F + col]);
                float2 prev = *p;
                *p = make_float2((prev.x + c[i][j][2]) * rin1,
                                 (prev.y + c[i][j][3]) * rin1);
            }
        }
    }
}

// ---------------- launcher ---------------------------------------------------
#define SMEM_NODE (5 * REG_BYTES)

extern "C" void kernel_launch(void* const* d_in, const int* in_sizes, int n_in,
                              void* d_out, int out_size) {
    const float* feat  = (const float*)d_in[0];
    const int*   src   = (const int*)  d_in[1];
    const int*   dst   = (const int*)  d_in[2];
    const int*   eattr = (const int*)  d_in[3];
    const float* w1    = (const float*)d_in[4];
    const float* w2    = (const float*)d_in[5];
    const float* v     = (const float*)d_in[6];
    const float* bond  = (const float*)d_in[7];
    float* out = (float*)d_out;

    static cudaStream_t s2 = nullptr;
    static cudaEvent_t evFork = nullptr, evJoin = nullptr;
    if (s2 == nullptr) {
        cudaStreamCreateWithFlags(&s2, cudaStreamNonBlocking);
        cudaEventCreateWithFlags(&evFork, cudaEventDisableTiming);
        cudaEventCreateWithFlags(&evJoin, cudaEventDisableTiming);
        cudaFuncSetAttribute(k_node_mma, cudaFuncAttributeMaxDynamicSharedMemorySize, SMEM_NODE);
        cudaFuncSetAttribute(k_fused,    cudaFuncAttributeMaxDynamicSharedMemorySize, SMEM_FUSED);
    }

    void *p_id, *p_od;
    cudaGetSymbolAddress(&p_id, g_indeg_i);
    cudaGetSymbolAddress(&p_od, g_outdeg_i);
    cudaMemsetAsync(p_id, 0, NN * sizeof(int));
    cudaMemsetAsync(p_od, 0, NN * sizeof(int));

    k_count <<<(NE + 255) / 256, 256>>>(src, dst);

    cudaEventRecord(evFork, 0);
    cudaStreamWaitEvent(s2, evFork, 0);

    k_scan1   <<<NB, 256, 0, s2>>>();
    k_scan2   <<<1, 512, 0, s2>>>();
    k_scan3   <<<NB, 256, 0, s2>>>();
    k_scatter <<<(NE + 255) / 256, 256, 0, s2>>>(src, dst, eattr);
    cudaEventRecord(evJoin, s2);

    k_wprep    <<<48, 256>>>(w1, w2, v);
    k_eprep    <<<32, 32>>>(bond);
    k_node_mma <<<NT, 512, SMEM_NODE>>>(feat, w2);

    cudaStreamWaitEvent(0, evJoin, 0);
    k_fused <<<NT, 1024, SMEM_FUSED>>>(bond, out);
}

// round 15
// speedup vs baseline: 1.2496x; 1.2496x over previous
#include <cuda_runtime.h>
#include <cuda_bf16.h>
#include <cstdint>

#define NN 100000
#define NE 800000
#define F  128
#define NT 782              // ceil(NN/128) node tiles
#define NB 391              // ceil(NN/256) scan blocks
#define LDA 136             // smem row stride in bf16 elements
#define REG_BYTES (128 * LDA * 2)   // 34816
#define PKF 192             // pack row stride in floats (512B hs + 256B slhp)

// fused kernel smem layout (bytes)
#define AS_OFF  0                        // 65536: fp32 As
#define AH_OFF  65536                    // 34816: bf16 hp
#define BH_OFF  (AH_OFF + REG_BYTES)     // 34816: bf16 v (hi)
#define EW_OFF  (BH_OFF + REG_BYTES)     // 16384
#define LEW_OFF (EW_OFF + 16384)         // 16384
#define SGN_OFF (LEW_OFF + 16384)        // 4096
#define CNT_OFF (SGN_OFF + 4096)
#define SMEM_FUSED (CNT_OFF + 16)        // 172048

// ---------------- scratch ----------------------------------------------------
__device__ int      g_indeg_i [NN];
__device__ int      g_outdeg_i[NN];
__device__ int      g_rowstart[NN];
__device__ int      g_cursor  [NN];
__device__ float    g_rin     [NN];
__device__ int      g_blksum  [512];
__device__ unsigned g_csr     [NE];
__device__ float    g_pack [(size_t)NN * PKF];   // per node: 128 f32 hs | 128 bf16 slhp
__device__ float    g_lew  [32 * F];
__device__ unsigned g_lewsgn[32 * 32];
__device__ __nv_bfloat16 g_w1h[F * F], g_w1l[F * F];
__device__ __nv_bfloat16 g_w2h[F * F], g_w2l[F * F];
__device__ __nv_bfloat16 g_vh [F * F], g_vl [F * F];

// ---------------- helpers ----------------------------------------------------
__device__ __forceinline__ uint32_t smem_to_u32(const void* p) {
    uint32_t a;
    asm("{ .reg .u64 t; cvta.to.shared.u64 t, %1; cvt.u32.u64 %0, t; }" : "=r"(a) : "l"(p));
    return a;
}

__device__ __forceinline__ void ldsm4(uint32_t& r0, uint32_t& r1, uint32_t& r2, uint32_t& r3,
                                      uint32_t addr) {
    asm volatile("ldmatrix.sync.aligned.m8n8.x4.shared.b16 {%0,%1,%2,%3}, [%4];"
                 : "=r"(r0), "=r"(r1), "=r"(r2), "=r"(r3) : "r"(addr));
}

__device__ __forceinline__ void mma_bf16(float* c, const uint32_t* a, const uint32_t* b) {
    asm volatile("mma.sync.aligned.m16n8k16.row.col.f32.bf16.bf16.f32 "
                 "{%0,%1,%2,%3}, {%4,%5,%6,%7}, {%8,%9}, {%0,%1,%2,%3};"
                 : "+f"(c[0]), "+f"(c[1]), "+f"(c[2]), "+f"(c[3])
                 : "r"(a[0]), "r"(a[1]), "r"(a[2]), "r"(a[3]), "r"(b[0]), "r"(b[1]));
}

__device__ __forceinline__ void split4(float4 x, uint2& H, uint2& L) {
    float xs[4] = {x.x, x.y, x.z, x.w};
    unsigned short h[4], l[4];
#pragma unroll
    for (int j = 0; j < 4; j++) {
        __nv_bfloat16 bh = __float2bfloat16(xs[j]);
        float r = xs[j] - __bfloat162float(bh);
        __nv_bfloat16 bl = __float2bfloat16(r);
        h[j] = __bfloat16_as_ushort(bh);
        l[j] = __bfloat16_as_ushort(bl);
    }
    H = make_uint2((uint32_t)h[0] | ((uint32_t)h[1] << 16),
                   (uint32_t)h[2] | ((uint32_t)h[3] << 16));
    L = make_uint2((uint32_t)l[0] | ((uint32_t)l[1] << 16),
                   (uint32_t)l[2] | ((uint32_t)l[3] << 16));
}

// ---------------- CSR build --------------------------------------------------
__global__ void k_count(const int* __restrict__ src, const int* __restrict__ dst) {
    int e = blockIdx.x * blockDim.x + threadIdx.x;
    if (e < NE) {
        atomicAdd(&g_indeg_i [dst[e]], 1);
        atomicAdd(&g_outdeg_i[src[e]], 1);
    }
}

__global__ void k_scan1() {
    __shared__ int swarp[8];
    int t = threadIdx.x, b = blockIdx.x;
    int i = b * 256 + t;
    int v = (i < NN) ? g_indeg_i[i] : 0;
    int x = v;
    int lane = t & 31, w = t >> 5;
#pragma unroll
    for (int o = 1; o < 32; o <<= 1) {
        int y = __shfl_up_sync(0xffffffffu, x, o);
        if (lane >= o) x += y;
    }
    if (lane == 31) swarp[w] = x;
    __syncthreads();
    if (w == 0) {
        int s = (lane < 8) ? swarp[lane] : 0;
#pragma unroll
        for (int o = 1; o < 8; o <<= 1) {
            int y = __shfl_up_sync(0xffffffffu, s, o);
            if (lane >= o) s += y;
        }
        if (lane < 8) swarp[lane] = s;
    }
    __syncthreads();
    int off = (w > 0) ? swarp[w - 1] : 0;
    if (i < NN) g_rowstart[i] = x - v + off;
    if (t == 255) g_blksum[b] = x + off;
}

__global__ void k_scan2() {
    __shared__ int swarp[16];
    int t = threadIdx.x;
    int v = (t < NB) ? g_blksum[t] : 0;
    int x = v;
    int lane = t & 31, w = t >> 5;
#pragma unroll
    for (int o = 1; o < 32; o <<= 1) {
        int y = __shfl_up_sync(0xffffffffu, x, o);
        if (lane >= o) x += y;
    }
    if (lane == 31) swarp[w] = x;
    __syncthreads();
    if (w == 0) {
        int s = (lane < 16) ? swarp[lane] : 0;
#pragma unroll
        for (int o = 1; o < 16; o <<= 1) {
            int y = __shfl_up_sync(0xffffffffu, s, o);
            if (lane >= o) s += y;
        }
        if (lane < 16) swarp[lane] = s;
    }
    __syncthreads();
    int off = (w > 0) ? swarp[w - 1] : 0;
    if (t < NB) g_blksum[t] = x - v + off;
}

__global__ void k_scan3() {
    int i = blockIdx.x * 256 + threadIdx.x;
    if (i < NN) {
        int r = g_rowstart[i] + g_blksum[blockIdx.x];
        g_rowstart[i] = r;
        g_cursor[i]   = r;
        g_rin[i]      = rsqrtf(fmaxf((float)g_indeg_i[i], 1.0f));
    }
}

__global__ void k_scatter(const int* __restrict__ src, const int* __restrict__ dst,
                          const int* __restrict__ eattr) {
    int e = blockIdx.x * blockDim.x + threadIdx.x;
    if (e < NE) {
        int d = dst[e];
        int pos = atomicAdd(&g_cursor[d], 1);
        g_csr[pos] = (unsigned)src[e] | ((unsigned)eattr[e] << 17);
    }
}

// ---------------- weights -> bf16 hi/lo B^T images --------------------------
__global__ void k_wprep(const float* __restrict__ w1, const float* __restrict__ w2,
                        const float* __restrict__ v) {
    int idx = blockIdx.x * 256 + threadIdx.x;
    if (idx >= 12288) return;
    int mat = idx >> 12;
    int rem = idx & 4095;
    int o  = rem >> 5;
    int k0 = (rem & 31) * 4;
    const float* src = (mat == 0) ? w1 : (mat == 1) ? w2 : v;
    __nv_bfloat16* hi = (mat == 0) ? g_w1h : (mat == 1) ? g_w2h : g_vh;
    __nv_bfloat16* lo = (mat == 0) ? g_w1l : (mat == 1) ? g_w2l : g_vl;
    float4 x;
    x.x = src[(size_t)(k0 + 0) * F + o];
    x.y = src[(size_t)(k0 + 1) * F + o];
    x.z = src[(size_t)(k0 + 2) * F + o];
    x.w = src[(size_t)(k0 + 3) * F + o];
    uint2 H, L; split4(x, H, L);
    *reinterpret_cast<uint2*>(&hi[o * F + k0]) = H;
    *reinterpret_cast<uint2*>(&lo[o * F + k0]) = L;
}

// ---------------- bond -> log|ew| + sign nibbles ----------------------------
__global__ void k_eprep(const float* __restrict__ bond) {
    int t = blockIdx.x;
    int g = threadIdx.x;
    float4 e = *reinterpret_cast<const float4*>(&bond[t * F + g * 4]);
    float4 le;
    le.x = __logf(fabsf(e.x));
    le.y = __logf(fabsf(e.y));
    le.z = __logf(fabsf(e.z));
    le.w = __logf(fabsf(e.w));
    *reinterpret_cast<float4*>(&g_lew[t * F + g * 4]) = le;
    unsigned sgn =  (__float_as_uint(e.x) >> 31)
                 | ((__float_as_uint(e.y) >> 31) << 1)
                 | ((__float_as_uint(e.z) >> 31) << 2)
                 | ((__float_as_uint(e.w) >> 31) << 3);
    g_lewsgn[t * 32 + g] = sgn;
}

// ---------------- fused dual node GEMM via mma.sync (512 threads) -----------
__global__ __launch_bounds__(512, 1) void k_node_mma(const float* __restrict__ feat,
                                                     const float* __restrict__ w2full) {
    extern __shared__ __align__(16) unsigned char smem[];
    __nv_bfloat16* Ah = (__nv_bfloat16*)smem;
    __nv_bfloat16* Al = Ah + 128 * LDA;
    __nv_bfloat16* Bw[3];
    Bw[0] = Al    + 128 * LDA;
    Bw[1] = Bw[0] + 128 * LDA;
    Bw[2] = Bw[1] + 128 * LDA;

    const int tid = threadIdx.x, lane = tid & 31, wid = tid >> 5;
    const int bid = blockIdx.x;

    {
        int r = tid >> 2, hf = tid & 3;
        int n = bid * 128 + r;
        float s = 0.0f;
        if (n < NN) s = rsqrtf(fmaxf((float)g_outdeg_i[n], 1.0f));
#pragma unroll
        for (int q = 0; q < 8; q++) {
            int k0 = hf * 32 + q * 4;
            float4 x = make_float4(0.f, 0.f, 0.f, 0.f);
            if (n < NN) {
                x = *reinterpret_cast<const float4*>(&feat[(size_t)n * F + k0]);
                x.x *= s; x.y *= s; x.z *= s; x.w *= s;
            }
            uint2 H, L; split4(x, H, L);
            *reinterpret_cast<uint2*>(&Ah[r * LDA + k0]) = H;
            *reinterpret_cast<uint2*>(&Al[r * LDA + k0]) = L;
        }
    }
    {
        const uint4* s0 = (const uint4*)g_w1h;
        const uint4* s1 = (const uint4*)g_w1l;
        const uint4* s2 = (const uint4*)g_w2h;
#pragma unroll
        for (int i = 0; i < 4; i++) {
            int idx = tid + i * 512;
            int row = idx >> 4, col = idx & 15;
            ((uint4*)Bw[0])[row * 17 + col] = s0[idx];
            ((uint4*)Bw[1])[row * 17 + col] = s1[idx];
            ((uint4*)Bw[2])[row * 17 + col] = s2[idx];
        }
    }
    __syncthreads();

    const int warp_m = wid & 1, warp_n = wid >> 1;
    const uint32_t sbase = smem_to_u32(smem);
    const uint32_t aAh = sbase, aAl = sbase + REG_BYTES;
    const int nl0 = (warp_n & 3) * 32;

    float c[4][4][4];
#pragma unroll
    for (int i = 0; i < 4; i++)
#pragma unroll
        for (int j = 0; j < 4; j++)
#pragma unroll
            for (int q = 0; q < 4; q++) c[i][j][q] = 0.f;

    const int npass = (warp_n < 4) ? 3 : 1;
#pragma unroll 1
    for (int p = 0; p < npass; p++) {
        uint32_t Abase = (p == 2) ? aAl : aAh;
        int bsel = (warp_n < 4) ? ((p == 1) ? 1 : 0) : 2;
        uint32_t Bbase = sbase + (uint32_t)(2 + bsel) * REG_BYTES;
#pragma unroll
        for (int ks = 0; ks < 8; ks++) {
            int k0 = ks * 16;
            uint32_t a[4][4];
#pragma unroll
            for (int i = 0; i < 4; i++) {
                int row = warp_m * 64 + i * 16 + (lane & 15);
                ldsm4(a[i][0], a[i][1], a[i][2], a[i][3],
                      Abase + (uint32_t)(row * LDA + k0 + ((lane >> 4) << 3)) * 2);
            }
            uint32_t b[4][2];
#pragma unroll
            for (int jj = 0; jj < 2; jj++) {
                int o = nl0 + jj * 16 + (lane & 7) + ((lane >> 4) << 3);
                uint32_t r0, r1, r2, r3;
                ldsm4(r0, r1, r2, r3,
                      Bbase + (uint32_t)(o * LDA + k0 + (((lane >> 3) & 1) << 3)) * 2);
                b[jj * 2][0] = r0; b[jj * 2][1] = r1;
                b[jj * 2 + 1][0] = r2; b[jj * 2 + 1][1] = r3;
            }
#pragma unroll
            for (int i = 0; i < 4; i++)
#pragma unroll
                for (int j = 0; j < 4; j++)
                    mma_bf16(c[i][j], a[i], b[j]);
        }
    }

    const int colbase = warp_n * 32;
    unsigned* packu = (unsigned*)g_pack;
#pragma unroll
    for (int i = 0; i < 4; i++) {
        int r0 = warp_m * 64 + i * 16 + (lane >> 2);
        int n0 = bid * 128 + r0;
        int n1 = n0 + 8;
#pragma unroll
        for (int j = 0; j < 4; j++) {
            int col = colbase + j * 8 + (lane & 3) * 2;
            if (col < 128) {
                if (n0 < NN)
                    *reinterpret_cast<float2*>(&g_pack[(size_t)n0 * PKF + col]) =
                        make_float2(c[i][j][0], c[i][j][1]);
                if (n1 < NN)
                    *reinterpret_cast<float2*>(&g_pack[(size_t)n1 * PKF + col]) =
                        make_float2(c[i][j][2], c[i][j][3]);
            } else {
                int c2 = col - 128;
                float2 bias = *reinterpret_cast<const float2*>(&w2full[(size_t)128 * F + c2]);
                if (n0 < NN) {
                    float t0 = tanhf(c[i][j][0] + bias.x);
                    float t1 = tanhf(c[i][j][1] + bias.y);
                    float l0 = __logf(fabsf(t0)) - 1.0f;
                    float l1 = __logf(fabsf(t1)) - 1.0f;
                    float s0 = (t0 < 0.f) ? -l0 : l0;
                    float s1 = (t1 < 0.f) ? -l1 : l1;
                    unsigned pk = (unsigned)__bfloat16_as_ushort(__float2bfloat16(s0))
                                | ((unsigned)__bfloat16_as_ushort(__float2bfloat16(s1)) << 16);
                    packu[(size_t)n0 * PKF + 128 + (c2 >> 1)] = pk;
                }
                if (n1 < NN) {
                    float t0 = tanhf(c[i][j][2] + bias.x);
                    float t1 = tanhf(c[i][j][3] + bias.y);
                    float l0 = __logf(fabsf(t0)) - 1.0f;
                    float l1 = __logf(fabsf(t1)) - 1.0f;
                    float s0 = (t0 < 0.f) ? -l0 : l0;
                    float s1 = (t1 < 0.f) ? -l1 : l1;
                    unsigned pk = (unsigned)__bfloat16_as_ushort(__float2bfloat16(s0))
                                | ((unsigned)__bfloat16_as_ushort(__float2bfloat16(s1)) << 16);
                    packu[(size_t)n1 * PKF + 128 + (c2 >> 1)] = pk;
                }
            }
        }
    }
}

// ---------------- fused gather + final GEMM (1024 threads, 1 CTA/SM) --------
// Phase 1: dynamic-row gather with CSR software prefetch -> As (fp32 smem)
//          + hp (bf16 smem image).
// Phase 2: single-pass MMA hp_bf16 @ v_hi; epilogue out = (As + C) * rin.
__global__ __launch_bounds__(1024, 1) void k_fused(const float* __restrict__ bond,
                                                   float* __restrict__ out) {
    extern __shared__ __align__(16) unsigned char smem[];
    float*        As  = (float*)(smem + AS_OFF);
    __nv_bfloat16* Ah = (__nv_bfloat16*)(smem + AH_OFF);
    float*        ewS  = (float*)(smem + EW_OFF);
    float*        lewS = (float*)(smem + LEW_OFF);
    unsigned*     sgnS = (unsigned*)(smem + SGN_OFF);
    int*          cnt  = (int*)(smem + CNT_OFF);

    const int tid = threadIdx.x, lane = tid & 31, wid = tid >> 5;
    const int bid = blockIdx.x;
    const int g = lane;

    // stage tables + v(hi) tile; init row counter
    {
        const uint4* s0 = (const uint4*)g_vh;
        uint4* d0 = (uint4*)(smem + BH_OFF);
#pragma unroll
        for (int i = 0; i < 2; i++) {
            int idx = tid + i * 1024;
            int row = idx >> 4, col = idx & 15;
            d0[row * 17 + col] = s0[idx];
        }
#pragma unroll
        for (int i = 0; i < 4; i++) {
            int idx = tid + i * 1024;
            ewS[idx]  = bond[idx];
            lewS[idx] = g_lew[idx];
        }
        if (tid < 1024) sgnS[tid] = g_lewsgn[tid];
        if (tid == 0) *cnt = 0;
    }
    __syncthreads();

    const float4* pk4 = (const float4*)g_pack;   // 48 float4 per row
    const uint2*  pk2 = (const uint2*)g_pack;    // 96 uint2 per row; slhp at +64
    const float4* ew4 = (const float4*)ewS;
    const float4* lw4 = (const float4*)lewS;

    // Phase 1: gather, dynamic row assignment + csr prefetch pipeline
    for (;;) {
        int r;
        if (lane == 0) r = atomicAdd(cnt, 1);
        r = __shfl_sync(0xffffffffu, r, 0);
        if (r >= 128) break;
        int n = bid * 128 + r;

        float4 as = make_float4(0.f, 0.f, 0.f, 0.f);
        float4 al = make_float4(0.f, 0.f, 0.f, 0.f);
        unsigned sg = 0;
        int deg = 0;

        if (n < NN) {
            int base = g_rowstart[n];
            deg = g_indeg_i[n];
            int i = 0;
            unsigned c0 = 0, c1 = 0;
            if (i + 2 <= deg) {
                c0 = __ldg(&g_csr[base]);
                c1 = __ldg(&g_csr[base + 1]);
            }
            for (; i + 2 <= deg; ) {
                // prefetch next pair before consuming current
                unsigned nc0 = 0, nc1 = 0;
                if (i + 4 <= deg) {
                    nc0 = __ldg(&g_csr[base + i + 2]);
                    nc1 = __ldg(&g_csr[base + i + 3]);
                }
                int s0 = c0 & 0x1FFFF, a0 = c0 >> 17;
                int s1 = c1 & 0x1FFFF, a1 = c1 >> 17;
                float4 h0 = __ldg(pk4 + (size_t)s0 * 48 + g);
                float4 h1 = __ldg(pk4 + (size_t)s1 * 48 + g);
                uint2  x0 = __ldg(pk2 + (size_t)s0 * 96 + 64 + g);
                uint2  x1 = __ldg(pk2 + (size_t)s1 * 96 + 64 + g);
                float4 e0 = ew4[a0 * 32 + g];
                float4 e1 = ew4[a1 * 32 + g];
                float4 w0 = lw4[a0 * 32 + g];
                float4 w1 = lw4[a1 * 32 + g];
                unsigned es = sgnS[a0 * 32 + g] ^ sgnS[a1 * 32 + g];

                as.x += h0.x*e0.x + h1.x*e1.x;
                as.y += h0.y*e0.y + h1.y*e1.y;
                as.z += h0.z*e0.z + h1.z*e1.z;
                as.w += h0.w*e0.w + h1.w*e1.w;

                float f00 = __uint_as_float((x0.x & 0xffffu) << 16);
                float f01 = __uint_as_float(x0.x & 0xffff0000u);
                float f02 = __uint_as_float((x0.y & 0xffffu) << 16);
                float f03 = __uint_as_float(x0.y & 0xffff0000u);
                float f10 = __uint_as_float((x1.x & 0xffffu) << 16);
                float f11 = __uint_as_float(x1.x & 0xffff0000u);
                float f12 = __uint_as_float((x1.y & 0xffffu) << 16);
                float f13 = __uint_as_float(x1.y & 0xffff0000u);

                al.x += (w0.x - fabsf(f00)) + (w1.x - fabsf(f10));
                al.y += (w0.y - fabsf(f01)) + (w1.y - fabsf(f11));
                al.z += (w0.z - fabsf(f02)) + (w1.z - fabsf(f12));
                al.w += (w0.w - fabsf(f03)) + (w1.w - fabsf(f13));

                unsigned b0 =  ((~(x0.x >> 15)) & 1u)
                            | (((~(x0.x >> 31)) & 1u) << 1)
                            | (((~(x0.y >> 15)) & 1u) << 2)
                            | (((~(x0.y >> 31)) & 1u) << 3);
                unsigned b1 =  ((~(x1.x >> 15)) & 1u)
                            | (((~(x1.x >> 31)) & 1u) << 1)
                            | (((~(x1.y >> 15)) & 1u) << 2)
                            | (((~(x1.y >> 31)) & 1u) << 3);
                sg ^= es ^ b0 ^ b1;

                c0 = nc0; c1 = nc1;
                i += 2;
            }
            if (i < deg) {
                unsigned cc = __ldg(&g_csr[base + i]);
                int s0 = cc & 0x1FFFF, a0 = cc >> 17;
                float4 h0 = __ldg(pk4 + (size_t)s0 * 48 + g);
                uint2  x0 = __ldg(pk2 + (size_t)s0 * 96 + 64 + g);
                float4 e0 = ew4[a0 * 32 + g];
                float4 w0 = lw4[a0 * 32 + g];
                unsigned es = sgnS[a0 * 32 + g];

                as.x += h0.x*e0.x; as.y += h0.y*e0.y;
                as.z += h0.z*e0.z; as.w += h0.w*e0.w;

                float f00 = __uint_as_float((x0.x & 0xffffu) << 16);
                float f01 = __uint_as_float(x0.x & 0xffff0000u);
                float f02 = __uint_as_float((x0.y & 0xffffu) << 16);
                float f03 = __uint_as_float(x0.y & 0xffff0000u);
                al.x += w0.x - fabsf(f00);
                al.y += w0.y - fabsf(f01);
                al.z += w0.z - fabsf(f02);
                al.w += w0.w - fabsf(f03);
                unsigned b0 =  ((~(x0.x >> 15)) & 1u)
                            | (((~(x0.x >> 31)) & 1u) << 1)
                            | (((~(x0.y >> 15)) & 1u) << 2)
                            | (((~(x0.y >> 31)) & 1u) << 3);
                sg ^= es ^ b0;
            }
        }

        *reinterpret_cast<float4*>(&As[r * 128 + g * 4]) = as;

        // hp = sign * exp(al + deg) -> bf16 smem image
        float hx = 0.f, hy = 0.f, hz = 0.f, hw = 0.f;
        if (n < NN) {
            float dc = (float)deg;
            hx = __expf(al.x + dc); if (sg & 1u) hx = -hx;
            hy = __expf(al.y + dc); if (sg & 2u) hy = -hy;
            hz = __expf(al.z + dc); if (sg & 4u) hz = -hz;
            hw = __expf(al.w + dc); if (sg & 8u) hw = -hw;
        }
        unsigned p0 = (unsigned)__bfloat16_as_ushort(__float2bfloat16(hx))
                    | ((unsigned)__bfloat16_as_ushort(__float2bfloat16(hy)) << 16);
        unsigned p1 = (unsigned)__bfloat16_as_ushort(__float2bfloat16(hz))
                    | ((unsigned)__bfloat16_as_ushort(__float2bfloat16(hw)) << 16);
        *reinterpret_cast<uint2*>(&Ah[r * LDA + g * 4]) = make_uint2(p0, p1);
    }
    __syncthreads();

    // Phase 2: single-pass MMA 128x128, 32 warps (4 x 8 of 32x16 tiles)
    const int warp_m = wid & 3, warp_n = wid >> 2;
    const uint32_t sbase = smem_to_u32(smem);
    const int nl0 = warp_n * 16;

    float c[2][2][4];
#pragma unroll
    for (int i = 0; i < 2; i++)
#pragma unroll
        for (int j = 0; j < 2; j++)
#pragma unroll
            for (int q = 0; q < 4; q++) c[i][j][q] = 0.f;

    {
        uint32_t Abase = sbase + AH_OFF;
        uint32_t Bbase = sbase + BH_OFF;
#pragma unroll
        for (int ks = 0; ks < 8; ks++) {
            int k0 = ks * 16;
            uint32_t a[2][4];
#pragma unroll
            for (int i = 0; i < 2; i++) {
                int row = warp_m * 32 + i * 16 + (lane & 15);
                ldsm4(a[i][0], a[i][1], a[i][2], a[i][3],
                      Abase + (uint32_t)(row * LDA + k0 + ((lane >> 4) << 3)) * 2);
            }
            uint32_t b[2][2];
            {
                int o = nl0 + (lane & 7) + ((lane >> 4) << 3);
                uint32_t r0, r1, r2, r3;
                ldsm4(r0, r1, r2, r3,
                      Bbase + (uint32_t)(o * LDA + k0 + (((lane >> 3) & 1) << 3)) * 2);
                b[0][0] = r0; b[0][1] = r1;
                b[1][0] = r2; b[1][1] = r3;
            }
#pragma unroll
            for (int i = 0; i < 2; i++)
#pragma unroll
                for (int j = 0; j < 2; j++)
                    mma_bf16(c[i][j], a[i], b[j]);
        }
    }

    // epilogue: out = (As + C) * rin
#pragma unroll
    for (int i = 0; i < 2; i++) {
        int r0 = warp_m * 32 + i * 16 + (lane >> 2);
        int r1 = r0 + 8;
        int n0 = bid * 128 + r0;
        int n1 = n0 + 8;
        float rin0 = (n0 < NN) ? g_rin[n0] : 0.f;
        float rin1 = (n1 < NN) ? g_rin[n1] : 0.f;
#pragma unroll
        for (int j = 0; j < 2; j++) {
            int col = nl0 + j * 8 + (lane & 3) * 2;
            if (n0 < NN) {
                float2 prev = *reinterpret_cast<float2*>(&As[r0 * 128 + col]);
                *reinterpret_cast<float2*>(&out[(size_t)n0 * F + col]) =
                    make_float2((prev.x + c[i][j][0]) * rin0,
                                (prev.y + c[i][j][1]) * rin0);
            }
            if (n1 < NN) {
                float2 prev = *reinterpret_cast<float2*>(&As[r1 * 128 + col]);
                *reinterpret_cast<float2*>(&out[(size_t)n1 * F + col]) =
                    make_float2((prev.x + c[i][j][2]) * rin1,
                                (prev.y + c[i][j][3]) * rin1);
            }
        }
    }
}

// ---------------- launcher ---------------------------------------------------
#define SMEM_NODE (5 * REG_BYTES)

extern "C" void kernel_launch(void* const* d_in, const int* in_sizes, int n_in,
                              void* d_out, int out_size) {
    const float* feat  = (const float*)d_in[0];
    const int*   src   = (const int*)  d_in[1];
    const int*   dst   = (const int*)  d_in[2];
    const int*   eattr = (const int*)  d_in[3];
    const float* w1    = (const float*)d_in[4];
    const float* w2    = (const float*)d_in[5];
    const float* v     = (const float*)d_in[6];
    const float* bond  = (const float*)d_in[7];
    float* out = (float*)d_out;

    static cudaStream_t s2 = nullptr;
    static cudaEvent_t evFork = nullptr, evJoin = nullptr;
    if (s2 == nullptr) {
        cudaStreamCreateWithFlags(&s2, cudaStreamNonBlocking);
        cudaEventCreateWithFlags(&evFork, cudaEventDisableTiming);
        cudaEventCreateWithFlags(&evJoin, cudaEventDisableTiming);
        cudaFuncSetAttribute(k_node_mma, cudaFuncAttributeMaxDynamicSharedMemorySize, SMEM_NODE);
        cudaFuncSetAttribute(k_fused,    cudaFuncAttributeMaxDynamicSharedMemorySize, SMEM_FUSED);
    }

    void *p_id, *p_od;
    cudaGetSymbolAddress(&p_id, g_indeg_i);
    cudaGetSymbolAddress(&p_od, g_outdeg_i);
    cudaMemsetAsync(p_id, 0, NN * sizeof(int));
    cudaMemsetAsync(p_od, 0, NN * sizeof(int));

    k_count <<<(NE + 255) / 256, 256>>>(src, dst);

    cudaEventRecord(evFork, 0);
    cudaStreamWaitEvent(s2, evFork, 0);

    k_scan1   <<<NB, 256, 0, s2>>>();
    k_scan2   <<<1, 512, 0, s2>>>();
    k_scan3   <<<NB, 256, 0, s2>>>();
    k_scatter <<<(NE + 255) / 256, 256, 0, s2>>>(src, dst, eattr);
    cudaEventRecord(evJoin, s2);

    k_wprep    <<<48, 256>>>(w1, w2, v);
    k_eprep    <<<32, 32>>>(bond);
    k_node_mma <<<NT, 512, SMEM_NODE>>>(feat, w2);

    cudaStreamWaitEvent(0, evJoin, 0);
    k_fused <<<NT, 1024, SMEM_FUSED>>>(bond, out);
}

// round 16
// speedup vs baseline: 1.8175x; 1.4544x over previous
#include <cuda_runtime.h>
#include <cuda_bf16.h>
#include <cstdint>

#define NN 100000
#define NE 800000
#define F  128
#define NT 782              // ceil(NN/128) node tiles
#define NB 391              // ceil(NN/256) scan blocks
#define LDA 136             // smem row stride in bf16 elements
#define REG_BYTES (128 * LDA * 2)   // 34816
#define PKF 192             // pack row stride in floats (512B hs + 256B slhp)

// fused kernel smem layout (bytes)
#define AS_OFF  0                        // 65536: fp32 As
#define AH_OFF  65536                    // 34816: bf16 hp
#define BH_OFF  (AH_OFF + REG_BYTES)     // 34816: bf16 v (hi)
#define EW_OFF  (BH_OFF + REG_BYTES)     // 16384
#define LEW_OFF (EW_OFF + 16384)         // 16384
#define SGN_OFF (LEW_OFF + 16384)        // 4096
#define CNT_OFF (SGN_OFF + 4096)
#define SMEM_FUSED (CNT_OFF + 16)        // 172048

// ---------------- scratch ----------------------------------------------------
__device__ int      g_indeg_i [NN];
__device__ int      g_outdeg_i[NN];
__device__ int      g_rowstart[NN];
__device__ int      g_cursor  [NN];
__device__ float    g_rin     [NN];
__device__ int      g_blksum  [512];
__device__ unsigned g_csr     [NE];
__device__ float    g_pack [(size_t)NN * PKF];   // per node: 128 f32 hs | 128 bf16 slhp
__device__ float    g_lew  [32 * F];
__device__ unsigned g_lewsgn[32 * 32];
__device__ __nv_bfloat16 g_w1h[F * F], g_w1l[F * F];
__device__ __nv_bfloat16 g_w2h[F * F], g_w2l[F * F];
__device__ __nv_bfloat16 g_vh [F * F], g_vl [F * F];

// ---------------- helpers ----------------------------------------------------
__device__ __forceinline__ uint32_t smem_to_u32(const void* p) {
    uint32_t a;
    asm("{ .reg .u64 t; cvta.to.shared.u64 t, %1; cvt.u32.u64 %0, t; }" : "=r"(a) : "l"(p));
    return a;
}

__device__ __forceinline__ void ldsm4(uint32_t& r0, uint32_t& r1, uint32_t& r2, uint32_t& r3,
                                      uint32_t addr) {
    asm volatile("ldmatrix.sync.aligned.m8n8.x4.shared.b16 {%0,%1,%2,%3}, [%4];"
                 : "=r"(r0), "=r"(r1), "=r"(r2), "=r"(r3) : "r"(addr));
}

__device__ __forceinline__ void mma_bf16(float* c, const uint32_t* a, const uint32_t* b) {
    asm volatile("mma.sync.aligned.m16n8k16.row.col.f32.bf16.bf16.f32 "
                 "{%0,%1,%2,%3}, {%4,%5,%6,%7}, {%8,%9}, {%0,%1,%2,%3};"
                 : "+f"(c[0]), "+f"(c[1]), "+f"(c[2]), "+f"(c[3])
                 : "r"(a[0]), "r"(a[1]), "r"(a[2]), "r"(a[3]), "r"(b[0]), "r"(b[1]));
}

__device__ __forceinline__ void split4(float4 x, uint2& H, uint2& L) {
    float xs[4] = {x.x, x.y, x.z, x.w};
    unsigned short h[4], l[4];
#pragma unroll
    for (int j = 0; j < 4; j++) {
        __nv_bfloat16 bh = __float2bfloat16(xs[j]);
        float r = xs[j] - __bfloat162float(bh);
        __nv_bfloat16 bl = __float2bfloat16(r);
        h[j] = __bfloat16_as_ushort(bh);
        l[j] = __bfloat16_as_ushort(bl);
    }
    H = make_uint2((uint32_t)h[0] | ((uint32_t)h[1] << 16),
                   (uint32_t)h[2] | ((uint32_t)h[3] << 16));
    L = make_uint2((uint32_t)l[0] | ((uint32_t)l[1] << 16),
                   (uint32_t)l[2] | ((uint32_t)l[3] << 16));
}

// ---------------- CSR build --------------------------------------------------
__global__ void k_count(const int* __restrict__ src, const int* __restrict__ dst) {
    int e = blockIdx.x * blockDim.x + threadIdx.x;
    if (e < NE) {
        atomicAdd(&g_indeg_i [dst[e]], 1);
        atomicAdd(&g_outdeg_i[src[e]], 1);
    }
}

__global__ void k_scan1() {
    __shared__ int swarp[8];
    int t = threadIdx.x, b = blockIdx.x;
    int i = b * 256 + t;
    int v = (i < NN) ? g_indeg_i[i] : 0;
    int x = v;
    int lane = t & 31, w = t >> 5;
#pragma unroll
    for (int o = 1; o < 32; o <<= 1) {
        int y = __shfl_up_sync(0xffffffffu, x, o);
        if (lane >= o) x += y;
    }
    if (lane == 31) swarp[w] = x;
    __syncthreads();
    if (w == 0) {
        int s = (lane < 8) ? swarp[lane] : 0;
#pragma unroll
        for (int o = 1; o < 8; o <<= 1) {
            int y = __shfl_up_sync(0xffffffffu, s, o);
            if (lane >= o) s += y;
        }
        if (lane < 8) swarp[lane] = s;
    }
    __syncthreads();
    int off = (w > 0) ? swarp[w - 1] : 0;
    if (i < NN) g_rowstart[i] = x - v + off;
    if (t == 255) g_blksum[b] = x + off;
}

__global__ void k_scan2() {
    __shared__ int swarp[16];
    int t = threadIdx.x;
    int v = (t < NB) ? g_blksum[t] : 0;
    int x = v;
    int lane = t & 31, w = t >> 5;
#pragma unroll
    for (int o = 1; o < 32; o <<= 1) {
        int y = __shfl_up_sync(0xffffffffu, x, o);
        if (lane >= o) x += y;
    }
    if (lane == 31) swarp[w] = x;
    __syncthreads();
    if (w == 0) {
        int s = (lane < 16) ? swarp[lane] : 0;
#pragma unroll
        for (int o = 1; o < 16; o <<= 1) {
            int y = __shfl_up_sync(0xffffffffu, s, o);
            if (lane >= o) s += y;
        }
        if (lane < 16) swarp[lane] = s;
    }
    __syncthreads();
    int off = (w > 0) ? swarp[w - 1] : 0;
    if (t < NB) g_blksum[t] = x - v + off;
}

__global__ void k_scan3() {
    int i = blockIdx.x * 256 + threadIdx.x;
    if (i < NN) {
        int r = g_rowstart[i] + g_blksum[blockIdx.x];
        g_rowstart[i] = r;
        g_cursor[i]   = r;
        g_rin[i]      = rsqrtf(fmaxf((float)g_indeg_i[i], 1.0f));
    }
}

__global__ void k_scatter(const int* __restrict__ src, const int* __restrict__ dst,
                          const int* __restrict__ eattr) {
    int e = blockIdx.x * blockDim.x + threadIdx.x;
    if (e < NE) {
        int d = dst[e];
        int pos = atomicAdd(&g_cursor[d], 1);
        g_csr[pos] = (unsigned)src[e] | ((unsigned)eattr[e] << 17);
    }
}

// ---------------- weights -> bf16 hi/lo B^T images --------------------------
__global__ void k_wprep(const float* __restrict__ w1, const float* __restrict__ w2,
                        const float* __restrict__ v) {
    int idx = blockIdx.x * 256 + threadIdx.x;
    if (idx >= 12288) return;
    int mat = idx >> 12;
    int rem = idx & 4095;
    int o  = rem >> 5;
    int k0 = (rem & 31) * 4;
    const float* src = (mat == 0) ? w1 : (mat == 1) ? w2 : v;
    __nv_bfloat16* hi = (mat == 0) ? g_w1h : (mat == 1) ? g_w2h : g_vh;
    __nv_bfloat16* lo = (mat == 0) ? g_w1l : (mat == 1) ? g_w2l : g_vl;
    float4 x;
    x.x = src[(size_t)(k0 + 0) * F + o];
    x.y = src[(size_t)(k0 + 1) * F + o];
    x.z = src[(size_t)(k0 + 2) * F + o];
    x.w = src[(size_t)(k0 + 3) * F + o];
    uint2 H, L; split4(x, H, L);
    *reinterpret_cast<uint2*>(&hi[o * F + k0]) = H;
    *reinterpret_cast<uint2*>(&lo[o * F + k0]) = L;
}

// ---------------- bond -> log|ew| + sign nibbles ----------------------------
__global__ void k_eprep(const float* __restrict__ bond) {
    int t = blockIdx.x;
    int g = threadIdx.x;
    float4 e = *reinterpret_cast<const float4*>(&bond[t * F + g * 4]);
    float4 le;
    le.x = __logf(fabsf(e.x));
    le.y = __logf(fabsf(e.y));
    le.z = __logf(fabsf(e.z));
    le.w = __logf(fabsf(e.w));
    *reinterpret_cast<float4*>(&g_lew[t * F + g * 4]) = le;
    unsigned sgn =  (__float_as_uint(e.x) >> 31)
                 | ((__float_as_uint(e.y) >> 31) << 1)
                 | ((__float_as_uint(e.z) >> 31) << 2)
                 | ((__float_as_uint(e.w) >> 31) << 3);
    g_lewsgn[t * 32 + g] = sgn;
}

// ---------------- fused dual node GEMM via mma.sync (512 threads) -----------
// w1 half: 3-pass bf16 split (feeds output). w2 half: 1-pass (feeds log path).
__global__ __launch_bounds__(512, 1) void k_node_mma(const float* __restrict__ feat,
                                                     const float* __restrict__ w2full) {
    extern __shared__ __align__(16) unsigned char smem[];
    __nv_bfloat16* Ah = (__nv_bfloat16*)smem;
    __nv_bfloat16* Al = Ah + 128 * LDA;
    __nv_bfloat16* Bw[3];
    Bw[0] = Al    + 128 * LDA;
    Bw[1] = Bw[0] + 128 * LDA;
    Bw[2] = Bw[1] + 128 * LDA;

    const int tid = threadIdx.x, lane = tid & 31, wid = tid >> 5;
    const int bid = blockIdx.x;

    {
        int r = tid >> 2, hf = tid & 3;
        int n = bid * 128 + r;
        float s = 0.0f;
        if (n < NN) s = rsqrtf(fmaxf((float)g_outdeg_i[n], 1.0f));
#pragma unroll
        for (int q = 0; q < 8; q++) {
            int k0 = hf * 32 + q * 4;
            float4 x = make_float4(0.f, 0.f, 0.f, 0.f);
            if (n < NN) {
                x = *reinterpret_cast<const float4*>(&feat[(size_t)n * F + k0]);
                x.x *= s; x.y *= s; x.z *= s; x.w *= s;
            }
            uint2 H, L; split4(x, H, L);
            *reinterpret_cast<uint2*>(&Ah[r * LDA + k0]) = H;
            *reinterpret_cast<uint2*>(&Al[r * LDA + k0]) = L;
        }
    }
    {
        const uint4* s0 = (const uint4*)g_w1h;
        const uint4* s1 = (const uint4*)g_w1l;
        const uint4* s2 = (const uint4*)g_w2h;
#pragma unroll
        for (int i = 0; i < 4; i++) {
            int idx = tid + i * 512;
            int row = idx >> 4, col = idx & 15;
            ((uint4*)Bw[0])[row * 17 + col] = s0[idx];
            ((uint4*)Bw[1])[row * 17 + col] = s1[idx];
            ((uint4*)Bw[2])[row * 17 + col] = s2[idx];
        }
    }
    __syncthreads();

    const int warp_m = wid & 1, warp_n = wid >> 1;
    const uint32_t sbase = smem_to_u32(smem);
    const uint32_t aAh = sbase, aAl = sbase + REG_BYTES;
    const int nl0 = (warp_n & 3) * 32;

    float c[4][4][4];
#pragma unroll
    for (int i = 0; i < 4; i++)
#pragma unroll
        for (int j = 0; j < 4; j++)
#pragma unroll
            for (int q = 0; q < 4; q++) c[i][j][q] = 0.f;

    const int npass = (warp_n < 4) ? 3 : 1;
#pragma unroll 1
    for (int p = 0; p < npass; p++) {
        uint32_t Abase = (p == 2) ? aAl : aAh;
        int bsel = (warp_n < 4) ? ((p == 1) ? 1 : 0) : 2;
        uint32_t Bbase = sbase + (uint32_t)(2 + bsel) * REG_BYTES;
#pragma unroll
        for (int ks = 0; ks < 8; ks++) {
            int k0 = ks * 16;
            uint32_t a[4][4];
#pragma unroll
            for (int i = 0; i < 4; i++) {
                int row = warp_m * 64 + i * 16 + (lane & 15);
                ldsm4(a[i][0], a[i][1], a[i][2], a[i][3],
                      Abase + (uint32_t)(row * LDA + k0 + ((lane >> 4) << 3)) * 2);
            }
            uint32_t b[4][2];
#pragma unroll
            for (int jj = 0; jj < 2; jj++) {
                int o = nl0 + jj * 16 + (lane & 7) + ((lane >> 4) << 3);
                uint32_t r0, r1, r2, r3;
                ldsm4(r0, r1, r2, r3,
                      Bbase + (uint32_t)(o * LDA + k0 + (((lane >> 3) & 1) << 3)) * 2);
                b[jj * 2][0] = r0; b[jj * 2][1] = r1;
                b[jj * 2 + 1][0] = r2; b[jj * 2 + 1][1] = r3;
            }
#pragma unroll
            for (int i = 0; i < 4; i++)
#pragma unroll
                for (int j = 0; j < 4; j++)
                    mma_bf16(c[i][j], a[i], b[j]);
        }
    }

    const int colbase = warp_n * 32;
    unsigned* packu = (unsigned*)g_pack;
#pragma unroll
    for (int i = 0; i < 4; i++) {
        int r0 = warp_m * 64 + i * 16 + (lane >> 2);
        int n0 = bid * 128 + r0;
        int n1 = n0 + 8;
#pragma unroll
        for (int j = 0; j < 4; j++) {
            int col = colbase + j * 8 + (lane & 3) * 2;
            if (col < 128) {
                if (n0 < NN)
                    *reinterpret_cast<float2*>(&g_pack[(size_t)n0 * PKF + col]) =
                        make_float2(c[i][j][0], c[i][j][1]);
                if (n1 < NN)
                    *reinterpret_cast<float2*>(&g_pack[(size_t)n1 * PKF + col]) =
                        make_float2(c[i][j][2], c[i][j][3]);
            } else {
                int c2 = col - 128;
                float2 bias = *reinterpret_cast<const float2*>(&w2full[(size_t)128 * F + c2]);
                if (n0 < NN) {
                    float t0 = tanhf(c[i][j][0] + bias.x);
                    float t1 = tanhf(c[i][j][1] + bias.y);
                    float l0 = __logf(fabsf(t0)) - 1.0f;
                    float l1 = __logf(fabsf(t1)) - 1.0f;
                    float s0 = (t0 < 0.f) ? -l0 : l0;
                    float s1 = (t1 < 0.f) ? -l1 : l1;
                    unsigned pk = (unsigned)__bfloat16_as_ushort(__float2bfloat16(s0))
                                | ((unsigned)__bfloat16_as_ushort(__float2bfloat16(s1)) << 16);
                    packu[(size_t)n0 * PKF + 128 + (c2 >> 1)] = pk;
                }
                if (n1 < NN) {
                    float t0 = tanhf(c[i][j][2] + bias.x);
                    float t1 = tanhf(c[i][j][3] + bias.y);
                    float l0 = __logf(fabsf(t0)) - 1.0f;
                    float l1 = __logf(fabsf(t1)) - 1.0f;
                    float s0 = (t0 < 0.f) ? -l0 : l0;
                    float s1 = (t1 < 0.f) ? -l1 : l1;
                    unsigned pk = (unsigned)__bfloat16_as_ushort(__float2bfloat16(s0))
                                | ((unsigned)__bfloat16_as_ushort(__float2bfloat16(s1)) << 16);
                    packu[(size_t)n1 * PKF + 128 + (c2 >> 1)] = pk;
                }
            }
        }
    }
}

// ---------------- fused gather + final GEMM (1024 threads) -------------------
// Phase 1: dynamic-row gather -> As (fp32 smem) + hp (bf16 smem, single image)
// Phase 2: single-pass MMA hp_bf16 @ v_hi; epilogue out = (As + C) * rin
__global__ __launch_bounds__(1024, 1) void k_fused(const float* __restrict__ bond,
                                                   float* __restrict__ out) {
    extern __shared__ __align__(16) unsigned char smem[];
    float*        As  = (float*)(smem + AS_OFF);
    __nv_bfloat16* Ah = (__nv_bfloat16*)(smem + AH_OFF);
    float*        ewS  = (float*)(smem + EW_OFF);
    float*        lewS = (float*)(smem + LEW_OFF);
    unsigned*     sgnS = (unsigned*)(smem + SGN_OFF);
    int*          cnt  = (int*)(smem + CNT_OFF);

    const int tid = threadIdx.x, lane = tid & 31, wid = tid >> 5;
    const int bid = blockIdx.x;
    const int g = lane;

    // stage tables + v(hi) tile; init row counter
    {
        const uint4* s0 = (const uint4*)g_vh;
        uint4* d0 = (uint4*)(smem + BH_OFF);
#pragma unroll
        for (int i = 0; i < 2; i++) {
            int idx = tid + i * 1024;
            int row = idx >> 4, col = idx & 15;
            d0[row * 17 + col] = s0[idx];
        }
#pragma unroll
        for (int i = 0; i < 4; i++) {
            int idx = tid + i * 1024;
            ewS[idx]  = bond[idx];
            lewS[idx] = g_lew[idx];
        }
        if (tid < 1024) sgnS[tid] = g_lewsgn[tid];
        if (tid == 0) *cnt = 0;
    }
    __syncthreads();

    const float4* pk4 = (const float4*)g_pack;   // 48 float4 per row
    const uint2*  pk2 = (const uint2*)g_pack;    // 96 uint2 per row; slhp at +64
    const float4* ew4 = (const float4*)ewS;
    const float4* lw4 = (const float4*)lewS;

    // Phase 1: gather, dynamic row assignment
    for (;;) {
        int r;
        if (lane == 0) r = atomicAdd(cnt, 1);
        r = __shfl_sync(0xffffffffu, r, 0);
        if (r >= 128) break;
        int n = bid * 128 + r;

        float4 as = make_float4(0.f, 0.f, 0.f, 0.f);
        float4 al = make_float4(0.f, 0.f, 0.f, 0.f);
        unsigned sg = 0;
        int deg = 0;

        if (n < NN) {
            int base = g_rowstart[n];
            deg = g_indeg_i[n];
            int i = 0;
            for (; i + 2 <= deg; i += 2) {
                unsigned c0 = __ldg(&g_csr[base + i]);
                unsigned c1 = __ldg(&g_csr[base + i + 1]);
                int s0 = c0 & 0x1FFFF, a0 = c0 >> 17;
                int s1 = c1 & 0x1FFFF, a1 = c1 >> 17;
                float4 h0 = __ldg(pk4 + (size_t)s0 * 48 + g);
                float4 h1 = __ldg(pk4 + (size_t)s1 * 48 + g);
                uint2  x0 = __ldg(pk2 + (size_t)s0 * 96 + 64 + g);
                uint2  x1 = __ldg(pk2 + (size_t)s1 * 96 + 64 + g);
                float4 e0 = ew4[a0 * 32 + g];
                float4 e1 = ew4[a1 * 32 + g];
                float4 w0 = lw4[a0 * 32 + g];
                float4 w1 = lw4[a1 * 32 + g];
                unsigned es = sgnS[a0 * 32 + g] ^ sgnS[a1 * 32 + g];

                as.x += h0.x*e0.x + h1.x*e1.x;
                as.y += h0.y*e0.y + h1.y*e1.y;
                as.z += h0.z*e0.z + h1.z*e1.z;
                as.w += h0.w*e0.w + h1.w*e1.w;

                float f00 = __uint_as_float((x0.x & 0xffffu) << 16);
                float f01 = __uint_as_float(x0.x & 0xffff0000u);
                float f02 = __uint_as_float((x0.y & 0xffffu) << 16);
                float f03 = __uint_as_float(x0.y & 0xffff0000u);
                float f10 = __uint_as_float((x1.x & 0xffffu) << 16);
                float f11 = __uint_as_float(x1.x & 0xffff0000u);
                float f12 = __uint_as_float((x1.y & 0xffffu) << 16);
                float f13 = __uint_as_float(x1.y & 0xffff0000u);

                al.x += (w0.x - fabsf(f00)) + (w1.x - fabsf(f10));
                al.y += (w0.y - fabsf(f01)) + (w1.y - fabsf(f11));
                al.z += (w0.z - fabsf(f02)) + (w1.z - fabsf(f12));
                al.w += (w0.w - fabsf(f03)) + (w1.w - fabsf(f13));

                unsigned b0 =  ((~(x0.x >> 15)) & 1u)
                            | (((~(x0.x >> 31)) & 1u) << 1)
                            | (((~(x0.y >> 15)) & 1u) << 2)
                            | (((~(x0.y >> 31)) & 1u) << 3);
                unsigned b1 =  ((~(x1.x >> 15)) & 1u)
                            | (((~(x1.x >> 31)) & 1u) << 1)
                            | (((~(x1.y >> 15)) & 1u) << 2)
                            | (((~(x1.y >> 31)) & 1u) << 3);
                sg ^= es ^ b0 ^ b1;
            }
            if (i < deg) {
                unsigned c0 = __ldg(&g_csr[base + i]);
                int s0 = c0 & 0x1FFFF, a0 = c0 >> 17;
                float4 h0 = __ldg(pk4 + (size_t)s0 * 48 + g);
                uint2  x0 = __ldg(pk2 + (size_t)s0 * 96 + 64 + g);
                float4 e0 = ew4[a0 * 32 + g];
                float4 w0 = lw4[a0 * 32 + g];
                unsigned es = sgnS[a0 * 32 + g];

                as.x += h0.x*e0.x; as.y += h0.y*e0.y;
                as.z += h0.z*e0.z; as.w += h0.w*e0.w;

                float f00 = __uint_as_float((x0.x & 0xffffu) << 16);
                float f01 = __uint_as_float(x0.x & 0xffff0000u);
                float f02 = __uint_as_float((x0.y & 0xffffu) << 16);
                float f03 = __uint_as_float(x0.y & 0xffff0000u);
                al.x += w0.x - fabsf(f00);
                al.y += w0.y - fabsf(f01);
                al.z += w0.z - fabsf(f02);
                al.w += w0.w - fabsf(f03);
                unsigned b0 =  ((~(x0.x >> 15)) & 1u)
                            | (((~(x0.x >> 31)) & 1u) << 1)
                            | (((~(x0.y >> 15)) & 1u) << 2)
                            | (((~(x0.y >> 31)) & 1u) << 3);
                sg ^= es ^ b0;
            }
        }

        *reinterpret_cast<float4*>(&As[r * 128 + g * 4]) = as;

        // hp = sign * exp(al + deg) -> bf16 (single image)
        float hx = 0.f, hy = 0.f, hz = 0.f, hw = 0.f;
        if (n < NN) {
            float dc = (float)deg;
            hx = __expf(al.x + dc); if (sg & 1u) hx = -hx;
            hy = __expf(al.y + dc); if (sg & 2u) hy = -hy;
            hz = __expf(al.z + dc); if (sg & 4u) hz = -hz;
            hw = __expf(al.w + dc); if (sg & 8u) hw = -hw;
        }
        unsigned p0 = (unsigned)__bfloat16_as_ushort(__float2bfloat16(hx))
                    | ((unsigned)__bfloat16_as_ushort(__float2bfloat16(hy)) << 16);
        unsigned p1 = (unsigned)__bfloat16_as_ushort(__float2bfloat16(hz))
                    | ((unsigned)__bfloat16_as_ushort(__float2bfloat16(hw)) << 16);
        *reinterpret_cast<uint2*>(&Ah[r * LDA + g * 4]) = make_uint2(p0, p1);
    }
    __syncthreads();

    // Phase 2: single-pass MMA 128x128, 32 warps (4 x 8 of 32x16 tiles)
    const int warp_m = wid & 3, warp_n = wid >> 2;
    const uint32_t sbase = smem_to_u32(smem);
    const int nl0 = warp_n * 16;

    float c[2][2][4];
#pragma unroll
    for (int i = 0; i < 2; i++)
#pragma unroll
        for (int j = 0; j < 2; j++)
#pragma unroll
            for (int q = 0; q < 4; q++) c[i][j][q] = 0.f;

    {
        uint32_t Abase = sbase + AH_OFF;
        uint32_t Bbase = sbase + BH_OFF;
#pragma unroll
        for (int ks = 0; ks < 8; ks++) {
            int k0 = ks * 16;
            uint32_t a[2][4];
#pragma unroll
            for (int i = 0; i < 2; i++) {
                int row = warp_m * 32 + i * 16 + (lane & 15);
                ldsm4(a[i][0], a[i][1], a[i][2], a[i][3],
                      Abase + (uint32_t)(row * LDA + k0 + ((lane >> 4) << 3)) * 2);
            }
            uint32_t b[2][2];
            {
                int o = nl0 + (lane & 7) + ((lane >> 4) << 3);
                uint32_t r0, r1, r2, r3;
                ldsm4(r0, r1, r2, r3,
                      Bbase + (uint32_t)(o * LDA + k0 + (((lane >> 3) & 1) << 3)) * 2);
                b[0][0] = r0; b[0][1] = r1;
                b[1][0] = r2; b[1][1] = r3;
            }
#pragma unroll
            for (int i = 0; i < 2; i++)
#pragma unroll
                for (int j = 0; j < 2; j++)
                    mma_bf16(c[i][j], a[i], b[j]);
        }
    }

    // epilogue: out = (As + C) * rin
#pragma unroll
    for (int i = 0; i < 2; i++) {
        int r0 = warp_m * 32 + i * 16 + (lane >> 2);
        int r1 = r0 + 8;
        int n0 = bid * 128 + r0;
        int n1 = n0 + 8;
        float rin0 = (n0 < NN) ? g_rin[n0] : 0.f;
        float rin1 = (n1 < NN) ? g_rin[n1] : 0.f;
#pragma unroll
        for (int j = 0; j < 2; j++) {
            int col = nl0 + j * 8 + (lane & 3) * 2;
            if (n0 < NN) {
                float2 prev = *reinterpret_cast<float2*>(&As[r0 * 128 + col]);
                *reinterpret_cast<float2*>(&out[(size_t)n0 * F + col]) =
                    make_float2((prev.x + c[i][j][0]) * rin0,
                                (prev.y + c[i][j][1]) * rin0);
            }
            if (n1 < NN) {
                float2 prev = *reinterpret_cast<float2*>(&As[r1 * 128 + col]);
                *reinterpret_cast<float2*>(&out[(size_t)n1 * F + col]) =
                    make_float2((prev.x + c[i][j][2]) * rin1,
                                (prev.y + c[i][j][3]) * rin1);
            }
        }
    }
}

// ---------------- launcher ---------------------------------------------------
#define SMEM_NODE (5 * REG_BYTES)

extern "C" void kernel_launch(void* const* d_in, const int* in_sizes, int n_in,
                              void* d_out, int out_size) {
    const float* feat  = (const float*)d_in[0];
    const int*   src   = (const int*)  d_in[1];
    const int*   dst   = (const int*)  d_in[2];
    const int*   eattr = (const int*)  d_in[3];
    const float* w1    = (const float*)d_in[4];
    const float* w2    = (const float*)d_in[5];
    const float* v     = (const float*)d_in[6];
    const float* bond  = (const float*)d_in[7];
    float* out = (float*)d_out;

    static cudaStream_t s2 = nullptr;
    static cudaEvent_t evFork = nullptr, evJoin = nullptr;
    if (s2 == nullptr) {
        cudaStreamCreateWithFlags(&s2, cudaStreamNonBlocking);
        cudaEventCreateWithFlags(&evFork, cudaEventDisableTiming);
        cudaEventCreateWithFlags(&evJoin, cudaEventDisableTiming);
        cudaFuncSetAttribute(k_node_mma, cudaFuncAttributeMaxDynamicSharedMemorySize, SMEM_NODE);
        cudaFuncSetAttribute(k_fused,    cudaFuncAttributeMaxDynamicSharedMemorySize, SMEM_FUSED);
    }

    void *p_id, *p_od;
    cudaGetSymbolAddress(&p_id, g_indeg_i);
    cudaGetSymbolAddress(&p_od, g_outdeg_i);
    cudaMemsetAsync(p_id, 0, NN * sizeof(int));
    cudaMemsetAsync(p_od, 0, NN * sizeof(int));

    k_count <<<(NE + 255) / 256, 256>>>(src, dst);

    cudaEventRecord(evFork, 0);
    cudaStreamWaitEvent(s2, evFork, 0);

    k_scan1   <<<NB, 256, 0, s2>>>();
    k_scan2   <<<1, 512, 0, s2>>>();
    k_scan3   <<<NB, 256, 0, s2>>>();
    k_scatter <<<(NE + 255) / 256, 256, 0, s2>>>(src, dst, eattr);
    cudaEventRecord(evJoin, s2);

    k_wprep    <<<48, 256>>>(w1, w2, v);
    k_eprep    <<<32, 32>>>(bond);
    k_node_mma <<<NT, 512, SMEM_NODE>>>(feat, w2);

    cudaStreamWaitEvent(0, evJoin, 0);
    k_fused <<<NT, 1024, SMEM_FUSED>>>(bond, out);
}

// round 17
// speedup vs baseline: 2.0809x; 1.1449x over previous
#include <cuda_runtime.h>
#include <cuda_bf16.h>
#include <cstdint>

#define NN 100000
#define NE 800000
#define F  128
#define NT 782              // ceil(NN/128) node tiles
#define NB 391              // ceil(NN/256) scan blocks
#define LDA 136             // smem row stride in bf16 elements
#define REG_BYTES (128 * LDA * 2)   // 34816
#define PKF 192             // pack row stride in floats (512B hs + 256B hp_bf16)

// fused kernel smem layout (bytes)
#define AS_OFF  0                        // 65536: fp32 As
#define AH_OFF  65536                    // 34816: bf16 hp
#define BH_OFF  (AH_OFF + REG_BYTES)     // 34816: bf16 v (hi)
#define EW_OFF  (BH_OFF + REG_BYTES)     // 16384: bond table fp32
#define CNT_OFF (EW_OFF + 16384)
#define SMEM_FUSED (CNT_OFF + 16)        // 151568

// ---------------- scratch ----------------------------------------------------
__device__ int      g_indeg_i [NN];
__device__ int      g_outdeg_i[NN];
__device__ int      g_rowstart[NN];
__device__ int      g_cursor  [NN];
__device__ float    g_rin     [NN];
__device__ int      g_blksum  [512];
__device__ unsigned g_csr     [NE];
__device__ float    g_pack [(size_t)NN * PKF];   // per node: 128 f32 hs | 128 bf16 hp
__device__ __nv_bfloat16 g_w1h[F * F], g_w1l[F * F];
__device__ __nv_bfloat16 g_w2h[F * F], g_w2l[F * F];
__device__ __nv_bfloat16 g_vh [F * F], g_vl [F * F];

// ---------------- helpers ----------------------------------------------------
__device__ __forceinline__ uint32_t smem_to_u32(const void* p) {
    uint32_t a;
    asm("{ .reg .u64 t; cvta.to.shared.u64 t, %1; cvt.u32.u64 %0, t; }" : "=r"(a) : "l"(p));
    return a;
}

__device__ __forceinline__ void ldsm4(uint32_t& r0, uint32_t& r1, uint32_t& r2, uint32_t& r3,
                                      uint32_t addr) {
    asm volatile("ldmatrix.sync.aligned.m8n8.x4.shared.b16 {%0,%1,%2,%3}, [%4];"
                 : "=r"(r0), "=r"(r1), "=r"(r2), "=r"(r3) : "r"(addr));
}

__device__ __forceinline__ void mma_bf16(float* c, const uint32_t* a, const uint32_t* b) {
    asm volatile("mma.sync.aligned.m16n8k16.row.col.f32.bf16.bf16.f32 "
                 "{%0,%1,%2,%3}, {%4,%5,%6,%7}, {%8,%9}, {%0,%1,%2,%3};"
                 : "+f"(c[0]), "+f"(c[1]), "+f"(c[2]), "+f"(c[3])
                 : "r"(a[0]), "r"(a[1]), "r"(a[2]), "r"(a[3]), "r"(b[0]), "r"(b[1]));
}

__device__ __forceinline__ void split4(float4 x, uint2& H, uint2& L) {
    float xs[4] = {x.x, x.y, x.z, x.w};
    unsigned short h[4], l[4];
#pragma unroll
    for (int j = 0; j < 4; j++) {
        __nv_bfloat16 bh = __float2bfloat16(xs[j]);
        float r = xs[j] - __bfloat162float(bh);
        __nv_bfloat16 bl = __float2bfloat16(r);
        h[j] = __bfloat16_as_ushort(bh);
        l[j] = __bfloat16_as_ushort(bl);
    }
    H = make_uint2((uint32_t)h[0] | ((uint32_t)h[1] << 16),
                   (uint32_t)h[2] | ((uint32_t)h[3] << 16));
    L = make_uint2((uint32_t)l[0] | ((uint32_t)l[1] << 16),
                   (uint32_t)l[2] | ((uint32_t)l[3] << 16));
}

__device__ __forceinline__ float bf16lo(unsigned u) {
    return __uint_as_float((u & 0xffffu) << 16);
}
__device__ __forceinline__ float bf16hi(unsigned u) {
    return __uint_as_float(u & 0xffff0000u);
}

// ---------------- CSR build --------------------------------------------------
__global__ void k_count(const int* __restrict__ src, const int* __restrict__ dst) {
    int e = blockIdx.x * blockDim.x + threadIdx.x;
    if (e < NE) {
        atomicAdd(&g_indeg_i [dst[e]], 1);
        atomicAdd(&g_outdeg_i[src[e]], 1);
    }
}

__global__ void k_scan1() {
    __shared__ int swarp[8];
    int t = threadIdx.x, b = blockIdx.x;
    int i = b * 256 + t;
    int v = (i < NN) ? g_indeg_i[i] : 0;
    int x = v;
    int lane = t & 31, w = t >> 5;
#pragma unroll
    for (int o = 1; o < 32; o <<= 1) {
        int y = __shfl_up_sync(0xffffffffu, x, o);
        if (lane >= o) x += y;
    }
    if (lane == 31) swarp[w] = x;
    __syncthreads();
    if (w == 0) {
        int s = (lane < 8) ? swarp[lane] : 0;
#pragma unroll
        for (int o = 1; o < 8; o <<= 1) {
            int y = __shfl_up_sync(0xffffffffu, s, o);
            if (lane >= o) s += y;
        }
        if (lane < 8) swarp[lane] = s;
    }
    __syncthreads();
    int off = (w > 0) ? swarp[w - 1] : 0;
    if (i < NN) g_rowstart[i] = x - v + off;
    if (t == 255) g_blksum[b] = x + off;
}

__global__ void k_scan2() {
    __shared__ int swarp[16];
    int t = threadIdx.x;
    int v = (t < NB) ? g_blksum[t] : 0;
    int x = v;
    int lane = t & 31, w = t >> 5;
#pragma unroll
    for (int o = 1; o < 32; o <<= 1) {
        int y = __shfl_up_sync(0xffffffffu, x, o);
        if (lane >= o) x += y;
    }
    if (lane == 31) swarp[w] = x;
    __syncthreads();
    if (w == 0) {
        int s = (lane < 16) ? swarp[lane] : 0;
#pragma unroll
        for (int o = 1; o < 16; o <<= 1) {
            int y = __shfl_up_sync(0xffffffffu, s, o);
            if (lane >= o) s += y;
        }
        if (lane < 16) swarp[lane] = s;
    }
    __syncthreads();
    int off = (w > 0) ? swarp[w - 1] : 0;
    if (t < NB) g_blksum[t] = x - v + off;
}

__global__ void k_scan3() {
    int i = blockIdx.x * 256 + threadIdx.x;
    if (i < NN) {
        int r = g_rowstart[i] + g_blksum[blockIdx.x];
        g_rowstart[i] = r;
        g_cursor[i]   = r;
        g_rin[i]      = rsqrtf(fmaxf((float)g_indeg_i[i], 1.0f));
    }
}

__global__ void k_scatter(const int* __restrict__ src, const int* __restrict__ dst,
                          const int* __restrict__ eattr) {
    int e = blockIdx.x * blockDim.x + threadIdx.x;
    if (e < NE) {
        int d = dst[e];
        int pos = atomicAdd(&g_cursor[d], 1);
        g_csr[pos] = (unsigned)src[e] | ((unsigned)eattr[e] << 17);
    }
}

// ---------------- weights -> bf16 hi/lo B^T images --------------------------
__global__ void k_wprep(const float* __restrict__ w1, const float* __restrict__ w2,
                        const float* __restrict__ v) {
    int idx = blockIdx.x * 256 + threadIdx.x;
    if (idx >= 12288) return;
    int mat = idx >> 12;
    int rem = idx & 4095;
    int o  = rem >> 5;
    int k0 = (rem & 31) * 4;
    const float* src = (mat == 0) ? w1 : (mat == 1) ? w2 : v;
    __nv_bfloat16* hi = (mat == 0) ? g_w1h : (mat == 1) ? g_w2h : g_vh;
    __nv_bfloat16* lo = (mat == 0) ? g_w1l : (mat == 1) ? g_w2l : g_vl;
    float4 x;
    x.x = src[(size_t)(k0 + 0) * F + o];
    x.y = src[(size_t)(k0 + 1) * F + o];
    x.z = src[(size_t)(k0 + 2) * F + o];
    x.w = src[(size_t)(k0 + 3) * F + o];
    uint2 H, L; split4(x, H, L);
    *reinterpret_cast<uint2*>(&hi[o * F + k0]) = H;
    *reinterpret_cast<uint2*>(&lo[o * F + k0]) = L;
}

// ---------------- fused dual node GEMM via mma.sync (512 threads) -----------
// w1 half: 3-pass bf16 split (feeds output). w2 half: 1-pass (feeds product).
__global__ __launch_bounds__(512, 1) void k_node_mma(const float* __restrict__ feat,
                                                     const float* __restrict__ w2full) {
    extern __shared__ __align__(16) unsigned char smem[];
    __nv_bfloat16* Ah = (__nv_bfloat16*)smem;
    __nv_bfloat16* Al = Ah + 128 * LDA;
    __nv_bfloat16* Bw[3];
    Bw[0] = Al    + 128 * LDA;
    Bw[1] = Bw[0] + 128 * LDA;
    Bw[2] = Bw[1] + 128 * LDA;

    const int tid = threadIdx.x, lane = tid & 31, wid = tid >> 5;
    const int bid = blockIdx.x;

    {
        int r = tid >> 2, hf = tid & 3;
        int n = bid * 128 + r;
        float s = 0.0f;
        if (n < NN) s = rsqrtf(fmaxf((float)g_outdeg_i[n], 1.0f));
#pragma unroll
        for (int q = 0; q < 8; q++) {
            int k0 = hf * 32 + q * 4;
            float4 x = make_float4(0.f, 0.f, 0.f, 0.f);
            if (n < NN) {
                x = *reinterpret_cast<const float4*>(&feat[(size_t)n * F + k0]);
                x.x *= s; x.y *= s; x.z *= s; x.w *= s;
            }
            uint2 H, L; split4(x, H, L);
            *reinterpret_cast<uint2*>(&Ah[r * LDA + k0]) = H;
            *reinterpret_cast<uint2*>(&Al[r * LDA + k0]) = L;
        }
    }
    {
        const uint4* s0 = (const uint4*)g_w1h;
        const uint4* s1 = (const uint4*)g_w1l;
        const uint4* s2 = (const uint4*)g_w2h;
#pragma unroll
        for (int i = 0; i < 4; i++) {
            int idx = tid + i * 512;
            int row = idx >> 4, col = idx & 15;
            ((uint4*)Bw[0])[row * 17 + col] = s0[idx];
            ((uint4*)Bw[1])[row * 17 + col] = s1[idx];
            ((uint4*)Bw[2])[row * 17 + col] = s2[idx];
        }
    }
    __syncthreads();

    const int warp_m = wid & 1, warp_n = wid >> 1;
    const uint32_t sbase = smem_to_u32(smem);
    const uint32_t aAh = sbase, aAl = sbase + REG_BYTES;
    const int nl0 = (warp_n & 3) * 32;

    float c[4][4][4];
#pragma unroll
    for (int i = 0; i < 4; i++)
#pragma unroll
        for (int j = 0; j < 4; j++)
#pragma unroll
            for (int q = 0; q < 4; q++) c[i][j][q] = 0.f;

    const int npass = (warp_n < 4) ? 3 : 1;
#pragma unroll 1
    for (int p = 0; p < npass; p++) {
        uint32_t Abase = (p == 2) ? aAl : aAh;
        int bsel = (warp_n < 4) ? ((p == 1) ? 1 : 0) : 2;
        uint32_t Bbase = sbase + (uint32_t)(2 + bsel) * REG_BYTES;
#pragma unroll
        for (int ks = 0; ks < 8; ks++) {
            int k0 = ks * 16;
            uint32_t a[4][4];
#pragma unroll
            for (int i = 0; i < 4; i++) {
                int row = warp_m * 64 + i * 16 + (lane & 15);
                ldsm4(a[i][0], a[i][1], a[i][2], a[i][3],
                      Abase + (uint32_t)(row * LDA + k0 + ((lane >> 4) << 3)) * 2);
            }
            uint32_t b[4][2];
#pragma unroll
            for (int jj = 0; jj < 2; jj++) {
                int o = nl0 + jj * 16 + (lane & 7) + ((lane >> 4) << 3);
                uint32_t r0, r1, r2, r3;
                ldsm4(r0, r1, r2, r3,
                      Bbase + (uint32_t)(o * LDA + k0 + (((lane >> 3) & 1) << 3)) * 2);
                b[jj * 2][0] = r0; b[jj * 2][1] = r1;
                b[jj * 2 + 1][0] = r2; b[jj * 2 + 1][1] = r3;
            }
#pragma unroll
            for (int i = 0; i < 4; i++)
#pragma unroll
                for (int j = 0; j < 4; j++)
                    mma_bf16(c[i][j], a[i], b[j]);
        }
    }

    const int colbase = warp_n * 32;
    unsigned* packu = (unsigned*)g_pack;
#pragma unroll
    for (int i = 0; i < 4; i++) {
        int r0 = warp_m * 64 + i * 16 + (lane >> 2);
        int n0 = bid * 128 + r0;
        int n1 = n0 + 8;
#pragma unroll
        for (int j = 0; j < 4; j++) {
            int col = colbase + j * 8 + (lane & 3) * 2;
            if (col < 128) {
                if (n0 < NN)
                    *reinterpret_cast<float2*>(&g_pack[(size_t)n0 * PKF + col]) =
                        make_float2(c[i][j][0], c[i][j][1]);
                if (n1 < NN)
                    *reinterpret_cast<float2*>(&g_pack[(size_t)n1 * PKF + col]) =
                        make_float2(c[i][j][2], c[i][j][3]);
            } else {
                int c2 = col - 128;
                float2 bias = *reinterpret_cast<const float2*>(&w2full[(size_t)128 * F + c2]);
                // store hp = tanh(acc+bias) directly as bf16x2 (product done in gather)
                if (n0 < NN) {
                    float t0 = tanhf(c[i][j][0] + bias.x);
                    float t1 = tanhf(c[i][j][1] + bias.y);
                    unsigned pk = (unsigned)__bfloat16_as_ushort(__float2bfloat16(t0))
                                | ((unsigned)__bfloat16_as_ushort(__float2bfloat16(t1)) << 16);
                    packu[(size_t)n0 * PKF + 128 + (c2 >> 1)] = pk;
                }
                if (n1 < NN) {
                    float t0 = tanhf(c[i][j][2] + bias.x);
                    float t1 = tanhf(c[i][j][3] + bias.y);
                    unsigned pk = (unsigned)__bfloat16_as_ushort(__float2bfloat16(t0))
                                | ((unsigned)__bfloat16_as_ushort(__float2bfloat16(t1)) << 16);
                    packu[(size_t)n1 * PKF + 128 + (c2 >> 1)] = pk;
                }
            }
        }
    }
}

// ---------------- fused gather + final GEMM (1024 threads) -------------------
// Phase 1: dynamic-row gather; sum AND product both accumulated directly in
//          registers (no log-space). -> As (fp32 smem) + hp (bf16 smem image)
// Phase 2: single-pass MMA hp_bf16 @ v_hi; epilogue out = (As + C) * rin
__global__ __launch_bounds__(1024, 1) void k_fused(const float* __restrict__ bond,
                                                   float* __restrict__ out) {
    extern __shared__ __align__(16) unsigned char smem[];
    float*        As  = (float*)(smem + AS_OFF);
    __nv_bfloat16* Ah = (__nv_bfloat16*)(smem + AH_OFF);
    float*        ewS = (float*)(smem + EW_OFF);
    int*          cnt = (int*)(smem + CNT_OFF);

    const int tid = threadIdx.x, lane = tid & 31, wid = tid >> 5;
    const int bid = blockIdx.x;
    const int g = lane;

    // stage bond table + v(hi) tile; init row counter
    {
        const uint4* s0 = (const uint4*)g_vh;
        uint4* d0 = (uint4*)(smem + BH_OFF);
#pragma unroll
        for (int i = 0; i < 2; i++) {
            int idx = tid + i * 1024;
            int row = idx >> 4, col = idx & 15;
            d0[row * 17 + col] = s0[idx];
        }
#pragma unroll
        for (int i = 0; i < 4; i++) {
            int idx = tid + i * 1024;
            ewS[idx] = bond[idx];
        }
        if (tid == 0) *cnt = 0;
    }
    __syncthreads();

    const float4* pk4 = (const float4*)g_pack;   // 48 float4 per row
    const uint2*  pk2 = (const uint2*)g_pack;    // 96 uint2 per row; hp at +64
    const float4* ew4 = (const float4*)ewS;

    // Phase 1: gather, dynamic row assignment, direct product accumulation
    for (;;) {
        int r;
        if (lane == 0) r = atomicAdd(cnt, 1);
        r = __shfl_sync(0xffffffffu, r, 0);
        if (r >= 128) break;
        int n = bid * 128 + r;

        float4 as = make_float4(0.f, 0.f, 0.f, 0.f);
        float4 ap = make_float4(1.f, 1.f, 1.f, 1.f);

        if (n < NN) {
            int base = g_rowstart[n];
            int deg  = g_indeg_i[n];
            int i = 0;
            for (; i + 2 <= deg; i += 2) {
                unsigned c0 = __ldg(&g_csr[base + i]);
                unsigned c1 = __ldg(&g_csr[base + i + 1]);
                int s0 = c0 & 0x1FFFF, a0 = c0 >> 17;
                int s1 = c1 & 0x1FFFF, a1 = c1 >> 17;
                float4 h0 = __ldg(pk4 + (size_t)s0 * 48 + g);
                float4 h1 = __ldg(pk4 + (size_t)s1 * 48 + g);
                uint2  x0 = __ldg(pk2 + (size_t)s0 * 96 + 64 + g);
                uint2  x1 = __ldg(pk2 + (size_t)s1 * 96 + 64 + g);
                float4 e0 = ew4[a0 * 32 + g];
                float4 e1 = ew4[a1 * 32 + g];

                as.x += h0.x*e0.x + h1.x*e1.x;
                as.y += h0.y*e0.y + h1.y*e1.y;
                as.z += h0.z*e0.z + h1.z*e1.z;
                as.w += h0.w*e0.w + h1.w*e1.w;

                ap.x *= (bf16lo(x0.x) * e0.x) * (bf16lo(x1.x) * e1.x);
                ap.y *= (bf16hi(x0.x) * e0.y) * (bf16hi(x1.x) * e1.y);
                ap.z *= (bf16lo(x0.y) * e0.z) * (bf16lo(x1.y) * e1.z);
                ap.w *= (bf16hi(x0.y) * e0.w) * (bf16hi(x1.y) * e1.w);
            }
            if (i < deg) {
                unsigned c0 = __ldg(&g_csr[base + i]);
                int s0 = c0 & 0x1FFFF, a0 = c0 >> 17;
                float4 h0 = __ldg(pk4 + (size_t)s0 * 48 + g);
                uint2  x0 = __ldg(pk2 + (size_t)s0 * 96 + 64 + g);
                float4 e0 = ew4[a0 * 32 + g];

                as.x += h0.x*e0.x; as.y += h0.y*e0.y;
                as.z += h0.z*e0.z; as.w += h0.w*e0.w;
                ap.x *= bf16lo(x0.x) * e0.x;
                ap.y *= bf16hi(x0.x) * e0.y;
                ap.z *= bf16lo(x0.y) * e0.z;
                ap.w *= bf16hi(x0.y) * e0.w;
            }
        } else {
            ap = make_float4(0.f, 0.f, 0.f, 0.f);
        }

        *reinterpret_cast<float4*>(&As[r * 128 + g * 4]) = as;

        unsigned p0 = (unsigned)__bfloat16_as_ushort(__float2bfloat16(ap.x))
                    | ((unsigned)__bfloat16_as_ushort(__float2bfloat16(ap.y)) << 16);
        unsigned p1 = (unsigned)__bfloat16_as_ushort(__float2bfloat16(ap.z))
                    | ((unsigned)__bfloat16_as_ushort(__float2bfloat16(ap.w)) << 16);
        *reinterpret_cast<uint2*>(&Ah[r * LDA + g * 4]) = make_uint2(p0, p1);
    }
    __syncthreads();

    // Phase 2: single-pass MMA 128x128, 32 warps (4 x 8 of 32x16 tiles)
    const int warp_m = wid & 3, warp_n = wid >> 2;
    const uint32_t sbase = smem_to_u32(smem);
    const int nl0 = warp_n * 16;

    float c[2][2][4];
#pragma unroll
    for (int i = 0; i < 2; i++)
#pragma unroll
        for (int j = 0; j < 2; j++)
#pragma unroll
            for (int q = 0; q < 4; q++) c[i][j][q] = 0.f;

    {
        uint32_t Abase = sbase + AH_OFF;
        uint32_t Bbase = sbase + BH_OFF;
#pragma unroll
        for (int ks = 0; ks < 8; ks++) {
            int k0 = ks * 16;
            uint32_t a[2][4];
#pragma unroll
            for (int i = 0; i < 2; i++) {
                int row = warp_m * 32 + i * 16 + (lane & 15);
                ldsm4(a[i][0], a[i][1], a[i][2], a[i][3],
                      Abase + (uint32_t)(row * LDA + k0 + ((lane >> 4) << 3)) * 2);
            }
            uint32_t b[2][2];
            {
                int o = nl0 + (lane & 7) + ((lane >> 4) << 3);
                uint32_t r0, r1, r2, r3;
                ldsm4(r0, r1, r2, r3,
                      Bbase + (uint32_t)(o * LDA + k0 + (((lane >> 3) & 1) << 3)) * 2);
                b[0][0] = r0; b[0][1] = r1;
                b[1][0] = r2; b[1][1] = r3;
            }
#pragma unroll
            for (int i = 0; i < 2; i++)
#pragma unroll
                for (int j = 0; j < 2; j++)
                    mma_bf16(c[i][j], a[i], b[j]);
        }
    }

    // epilogue: out = (As + C) * rin
#pragma unroll
    for (int i = 0; i < 2; i++) {
        int r0 = warp_m * 32 + i * 16 + (lane >> 2);
        int r1 = r0 + 8;
        int n0 = bid * 128 + r0;
        int n1 = n0 + 8;
        float rin0 = (n0 < NN) ? g_rin[n0] : 0.f;
        float rin1 = (n1 < NN) ? g_rin[n1] : 0.f;
#pragma unroll
        for (int j = 0; j < 2; j++) {
            int col = nl0 + j * 8 + (lane & 3) * 2;
            if (n0 < NN) {
                float2 prev = *reinterpret_cast<float2*>(&As[r0 * 128 + col]);
                *reinterpret_cast<float2*>(&out[(size_t)n0 * F + col]) =
                    make_float2((prev.x + c[i][j][0]) * rin0,
                                (prev.y + c[i][j][1]) * rin0);
            }
            if (n1 < NN) {
                float2 prev = *reinterpret_cast<float2*>(&As[r1 * 128 + col]);
                *reinterpret_cast<float2*>(&out[(size_t)n1 * F + col]) =
                    make_float2((prev.x + c[i][j][2]) * rin1,
                                (prev.y + c[i][j][3]) * rin1);
            }
        }
    }
}

// ---------------- launcher ---------------------------------------------------
#define SMEM_NODE (5 * REG_BYTES)

extern "C" void kernel_launch(void* const* d_in, const int* in_sizes, int n_in,
                              void* d_out, int out_size) {
    const float* feat  = (const float*)d_in[0];
    const int*   src   = (const int*)  d_in[1];
    const int*   dst   = (const int*)  d_in[2];
    const int*   eattr = (const int*)  d_in[3];
    const float* w1    = (const float*)d_in[4];
    const float* w2    = (const float*)d_in[5];
    const float* v     = (const float*)d_in[6];
    const float* bond  = (const float*)d_in[7];
    float* out = (float*)d_out;

    static cudaStream_t s2 = nullptr;
    static cudaEvent_t evFork = nullptr, evJoin = nullptr;
    if (s2 == nullptr) {
        cudaStreamCreateWithFlags(&s2, cudaStreamNonBlocking);
        cudaEventCreateWithFlags(&evFork, cudaEventDisableTiming);
        cudaEventCreateWithFlags(&evJoin, cudaEventDisableTiming);
        cudaFuncSetAttribute(k_node_mma, cudaFuncAttributeMaxDynamicSharedMemorySize, SMEM_NODE);
        cudaFuncSetAttribute(k_fused,    cudaFuncAttributeMaxDynamicSharedMemorySize, SMEM_FUSED);
    }

    void *p_id, *p_od;
    cudaGetSymbolAddress(&p_id, g_indeg_i);
    cudaGetSymbolAddress(&p_od, g_outdeg_i);
    cudaMemsetAsync(p_id, 0, NN * sizeof(int));
    cudaMemsetAsync(p_od, 0, NN * sizeof(int));

    k_count <<<(NE + 255) / 256, 256>>>(src, dst);

    cudaEventRecord(evFork, 0);
    cudaStreamWaitEvent(s2, evFork, 0);

    k_scan1   <<<NB, 256, 0, s2>>>();
    k_scan2   <<<1, 512, 0, s2>>>();
    k_scan3   <<<NB, 256, 0, s2>>>();
    k_scatter <<<(NE + 255) / 256, 256, 0, s2>>>(src, dst, eattr);
    cudaEventRecord(evJoin, s2);

    k_wprep    <<<48, 256>>>(w1, w2, v);
    k_node_mma <<<NT, 512, SMEM_NODE>>>(feat, w2);

    cudaStreamWaitEvent(0, evJoin, 0);
    k_fused <<<NT, 1024, SMEM_FUSED>>>(bond, out);
}